// round 8
// baseline (speedup 1.0000x reference)
#include <cuda_runtime.h>
#include <math.h>

#define H 256
#define W 256
#define T 48
#define HWT (H*W*T)

// Output tile per block
#define OH 8
#define OW 8
#define OT 12
#define TT 2            // t-outputs per thread (register blocking)
#define NTHREADS 768    // 2 offset-groups x (8 tx * 8 ty * 6 tg)

// Halo'ed SMEM tile
#define HY 14           // OH + 6
#define HX 14           // OW + 6
#define HT 16           // OT + 4
#define ROWS (HY*HX)    // 196
#define PLANE (ROWS*HT) // 3136
#define NCH 18          // 9 scaled-guidance + 3 estimands + 3 variance + 3 images
#define SMEM_FLOATS (NCH*PLANE)   // 56448 floats -> 225792 bytes
#define SMEM_PAIRS (SMEM_FLOATS/2)

#define NL (TT + 4)     // 6 t-lanes loaded per row

// even rotation: keeps (jj, jj+1) pairs 8B-aligned & contiguous, and gives
// per-phase (16-lane) bank-conflict freedom for LDS.64
#define PHI2(x, y) (((((x) >> 1) & 3) + (((y) & 1) << 2)) << 1)

typedef unsigned long long u64;

// ---- Blackwell packed f32x2 helpers (each half rounds rn == scalar op) ----
__device__ __forceinline__ u64 pk2(float lo, float hi) {
    u64 u; asm("mov.b64 %0, {%1,%2};" : "=l"(u) : "f"(lo), "f"(hi)); return u;
}
__device__ __forceinline__ float2 up2(u64 u) {
    float2 v; asm("mov.b64 {%0,%1}, %2;" : "=f"(v.x), "=f"(v.y) : "l"(u)); return v;
}
__device__ __forceinline__ u64 fma2_(u64 a, u64 b, u64 c) {
    u64 d; asm("fma.rn.f32x2 %0, %1, %2, %3;" : "=l"(d) : "l"(a), "l"(b), "l"(c)); return d;
}
__device__ __forceinline__ u64 mul2_(u64 a, u64 b) {
    u64 d; asm("mul.rn.f32x2 %0, %1, %2;" : "=l"(d) : "l"(a), "l"(b)); return d;
}
__device__ __forceinline__ u64 add2_(u64 a, u64 b) {
    u64 d; asm("add.rn.f32x2 %0, %1, %2;" : "=l"(d) : "l"(a), "l"(b)); return d;
}

__global__ __launch_bounds__(NTHREADS, 1)
void denoise_kernel(const float* __restrict__ images,
                    const float* __restrict__ guidance,
                    const float* __restrict__ estimands,
                    const float* __restrict__ variance,
                    const float* __restrict__ sigma_inv,
                    const int*   __restrict__ spp_ptr,
                    float* __restrict__ out)
{
    extern __shared__ float sm[];
    __shared__ float ssig[9];   // sqrt(sigma_inv[c] * log2(e))

    const int tid = threadIdx.x;
    const int w0 = blockIdx.x * OW;
    const int h0 = blockIdx.y * OH;
    const int t0 = blockIdx.z * OT;

    if (tid < 9) {
        ssig[tid] = sqrtf(__fmul_rn(sigma_inv[tid], 1.4426950408889634f));
    }
    const float sppf = (float)spp_ptr[0];
    const float T2f  = (float)(2.8070337683438042 * 2.8070337683438042);
    __syncthreads();

    // ---------------- cooperative fill of halo'ed tile (paired) ----------
    #pragma unroll 4
    for (int it = 0; it < (SMEM_PAIRS + NTHREADS - 1) / NTHREADS; ++it) {  // 37 iters
        int idx = tid + it * NTHREADS;
        if (idx < SMEM_PAIRS) {
            int jp  = idx & 7;           // pair index in row
            int j   = jp << 1;           // even t slot (pre-rotation)
            int rid = idx >> 3;          // (c, y, x)
            int c   = rid / ROWS;
            int yx  = rid - c * ROWS;
            int y   = yx / HX;
            int x   = yx - y * HX;
            int hg = h0 + y - 3;
            int wg = w0 + x - 3;
            int tg_ = t0 + j - 2;        // even
            bool inb = ((unsigned)hg < H) & ((unsigned)wg < W) & ((unsigned)tg_ < T);
            int gidx = (hg * W + wg) * T + tg_;
            float2 val;
            if (c < 9) {
                if (inb) {
                    float2 g = *(const float2*)(guidance + c * HWT + gidx);
                    val.x = g.x * ssig[c]; val.y = g.y * ssig[c];
                } else { val.x = 0.f; val.y = 0.f; }
            } else if (c < 12) {
                if (inb) val = *(const float2*)(estimands + (c - 9) * HWT + gidx);
                else     { val.x = -2.f; val.y = -2.f; }
            } else if (c < 15) {
                if (inb) val = *(const float2*)(variance + (c - 12) * HWT + gidx);
                else     { val.x = 0.f; val.y = 0.f; }
            } else {
                if (inb) val = *(const float2*)(images + (c - 15) * HWT + gidx);
                else     { val.x = 0.f; val.y = 0.f; }
            }
            int slot = (j + PHI2(x, y)) & 15;    // even -> 8B aligned
            *(float2*)(sm + c * PLANE + (y * HX + x) * HT + slot) = val;
        }
    }
    __syncthreads();

    // ---------------- per-thread decomposition ----------------
    const int og  = (tid >= 384) ? 1 : 0;
    const int lt  = tid - og * 384;
    const int tg  = lt >> 6;          // 0..5
    const int rr  = lt & 63;
    const int ty  = rr >> 3;
    const int tx  = rr & 7;
    const int tgb = tg * TT;          // even
    const int o0  = og ? 25 : 0;      // spatial-offset range [o0, o1)
    const int o1  = og ? 49 : 25;

    // packed constants
    const u64 NEG1 = pk2(-1.0f, -1.0f);
    const u64 SPP2 = pk2(sppf, sppf);
    const u64 T22  = pk2(T2f, T2f);

    // center values as packed {tt=0, tt=1} pairs (lanes tgb+2, tgb+3 are an
    // aligned even pair -> one LDS.64 each)
    u64 gcp[9], ecp[3], vcp[3];
    float Pc[TT];
    {
        int yc = ty + 3, xc = tx + 3;
        int ph = PHI2(xc, yc);
        int slc = (yc * HX + xc) * HT + ((tgb + 2 + ph) & 15);
        float p0v = 0.0f, p1v = 0.0f;
        #pragma unroll
        for (int c = 0; c < 9; ++c) {
            gcp[c] = *(const u64*)(sm + c * PLANE + slc);
            float2 g = up2(gcp[c]);
            p0v = fmaf(g.x, g.x, p0v);     // same chain order as Pn2 halves
            p1v = fmaf(g.y, g.y, p1v);
        }
        Pc[0] = p0v; Pc[1] = p1v;
        #pragma unroll
        for (int c = 0; c < 3; ++c) ecp[c] = *(const u64*)(sm + (9 + c) * PLANE + slc);
        #pragma unroll
        for (int c = 0; c < 3; ++c) vcp[c] = *(const u64*)(sm + (12 + c) * PLANE + slc);
    }

    float num0[TT], num1[TT], num2[TT], den[TT];
    #pragma unroll
    for (int tt = 0; tt < TT; ++tt) { num0[tt] = 0.f; num1[tt] = 0.f; num2[tt] = 0.f; den[tt] = 0.f; }

    // ---------------- main loop over this group's spatial offsets --------
    int dy = o0 / 7, dx = o0 - 7 * (o0 / 7);
    #pragma unroll 1
    for (int o = o0; o < o1; ++o) {
        int y = ty + dy;
        int x = tx + dx;
        int rowoff = (y * HX + x) * HT;
        int ph = PHI2(x, y);
        // three even pair bases, contiguous 8B each (wrap never splits a pair)
        int p0 = rowoff + ((tgb + 0 + ph) & 15);
        int p1 = rowoff + ((tgb + 2 + ph) & 15);
        int p2 = rowoff + ((tgb + 4 + ph) & 15);

        // ---- guidance: packed dot/norm accumulators ----
        // A2[k] = { sum_c row[2k]*gc[c][0], sum_c row[2k+1]*gc[c][1] }
        //   -> covers (tt0, even dt) and (tt1, even dt)
        // dotS[0..3] = scalar odd-dt combos
        u64 Pn2[3] = {0, 0, 0};
        u64 A2[3]  = {0, 0, 0};
        float dotS0 = 0.f, dotS1 = 0.f, dotS2 = 0.f, dotS3 = 0.f;

        #pragma unroll
        for (int c = 0; c < 9; ++c) {
            const float* sc = sm + c * PLANE;
            u64 r0 = *(const u64*)(sc + p0);
            u64 r1 = *(const u64*)(sc + p1);
            u64 r2 = *(const u64*)(sc + p2);
            Pn2[0] = fma2_(r0, r0, Pn2[0]);
            Pn2[1] = fma2_(r1, r1, Pn2[1]);
            Pn2[2] = fma2_(r2, r2, Pn2[2]);
            A2[0] = fma2_(r0, gcp[c], A2[0]);
            A2[1] = fma2_(r1, gcp[c], A2[1]);
            A2[2] = fma2_(r2, gcp[c], A2[2]);
            float2 f0 = up2(r0), f1 = up2(r1), f2 = up2(r2);
            float2 gh = up2(gcp[c]);
            dotS0 = fmaf(f0.y, gh.x, dotS0);   // (tt0, dt1) lane1
            dotS1 = fmaf(f1.y, gh.x, dotS1);   // (tt0, dt3) lane3
            dotS2 = fmaf(f1.x, gh.y, dotS2);   // (tt1, dt1) lane2
            dotS3 = fmaf(f2.x, gh.y, dotS3);   // (tt1, dt3) lane4
        }

        // ---- z-test: per-channel eager, fmax accumulation (bit-exact rn) ----
        float fz[TT][5];
        #pragma unroll
        for (int tt = 0; tt < TT; ++tt)
            #pragma unroll
            for (int dt = 0; dt < 5; ++dt) fz[tt][dt] = -1.f;

        #pragma unroll
        for (int c = 0; c < 3; ++c) {
            const float* se = sm + (9 + c)  * PLANE;
            const float* sv = sm + (12 + c) * PLANE;
            u64 e0 = *(const u64*)(se + p0);
            u64 e1 = *(const u64*)(se + p1);
            u64 e2 = *(const u64*)(se + p2);
            u64 v0 = *(const u64*)(sv + p0);
            u64 v1 = *(const u64*)(sv + p1);
            u64 v2 = *(const u64*)(sv + p2);
            // packed: m = l - r where l=(e-ec)^2*spp, r=T2*(v+vc); each half
            // is the exact rn sequence of the reference.
            #pragma unroll
            for (int k = 0; k < 3; ++k) {
                u64 ek = (k == 0) ? e0 : (k == 1) ? e1 : e2;
                u64 vk = (k == 0) ? v0 : (k == 1) ? v1 : v2;
                u64 d2 = fma2_(ecp[c], NEG1, ek);        // e - ec
                u64 q2 = mul2_(d2, d2);
                u64 l2 = mul2_(q2, SPP2);
                u64 s2 = add2_(vk, vcp[c]);
                u64 r2v = mul2_(T22, s2);
                u64 m2 = fma2_(r2v, NEG1, l2);           // l - r
                float2 m = up2(m2);
                fz[0][2 * k] = fmaxf(fz[0][2 * k], m.x); // (tt0, dt=2k)
                fz[1][2 * k] = fmaxf(fz[1][2 * k], m.y); // (tt1, dt=2k)
            }
            // scalar odd-dt combos: lanes 1,3 (tt0) and 2,4 (tt1)
            float2 fe0 = up2(e0), fe1 = up2(e1), fe2 = up2(e2);
            float2 fv0 = up2(v0), fv1 = up2(v1), fv2 = up2(v2);
            float2 ech = up2(ecp[c]), vch = up2(vcp[c]);
            {   // (tt0, dt1): lane1
                float d = __fsub_rn(fe0.y, ech.x);
                float l = __fmul_rn(__fmul_rn(d, d), sppf);
                float r = __fmul_rn(T2f, __fadd_rn(fv0.y, vch.x));
                fz[0][1] = fmaxf(fz[0][1], __fsub_rn(l, r));
            }
            {   // (tt0, dt3): lane3
                float d = __fsub_rn(fe1.y, ech.x);
                float l = __fmul_rn(__fmul_rn(d, d), sppf);
                float r = __fmul_rn(T2f, __fadd_rn(fv1.y, vch.x));
                fz[0][3] = fmaxf(fz[0][3], __fsub_rn(l, r));
            }
            {   // (tt1, dt1): lane2
                float d = __fsub_rn(fe1.x, ech.y);
                float l = __fmul_rn(__fmul_rn(d, d), sppf);
                float r = __fmul_rn(T2f, __fadd_rn(fv1.x, vch.y));
                fz[1][1] = fmaxf(fz[1][1], __fsub_rn(l, r));
            }
            {   // (tt1, dt3): lane4
                float d = __fsub_rn(fe2.x, ech.y);
                float l = __fmul_rn(__fmul_rn(d, d), sppf);
                float r = __fmul_rn(T2f, __fadd_rn(fv2.x, vch.y));
                fz[1][3] = fmaxf(fz[1][3], __fsub_rn(l, r));
            }
        }

        // ---- unpack dot / Pn lanes (register-half reads, ~free) ----
        float2 pn0 = up2(Pn2[0]), pn1 = up2(Pn2[1]), pn2 = up2(Pn2[2]);
        float PnL[NL] = { pn0.x, pn0.y, pn1.x, pn1.y, pn2.x, pn2.y };
        float2 a0 = up2(A2[0]), a1 = up2(A2[1]), a2 = up2(A2[2]);
        float dotv[TT][5];
        dotv[0][0] = a0.x; dotv[0][2] = a1.x; dotv[0][4] = a2.x;
        dotv[1][0] = a0.y; dotv[1][2] = a1.y; dotv[1][4] = a2.y;
        dotv[0][1] = dotS0; dotv[0][3] = dotS1;
        dotv[1][1] = dotS2; dotv[1][3] = dotS3;

        // ---- image lanes ----
        float i0[NL], i1[NL], i2[NL];
        {
            const float* s0 = sm + 15 * PLANE;
            const float* s1 = sm + 16 * PLANE;
            const float* s2 = sm + 17 * PLANE;
            float2 b0 = *(const float2*)(s0 + p0);
            float2 b1 = *(const float2*)(s0 + p1);
            float2 b2 = *(const float2*)(s0 + p2);
            i0[0]=b0.x; i0[1]=b0.y; i0[2]=b1.x; i0[3]=b1.y; i0[4]=b2.x; i0[5]=b2.y;
            float2 c0 = *(const float2*)(s1 + p0);
            float2 c1 = *(const float2*)(s1 + p1);
            float2 c2 = *(const float2*)(s1 + p2);
            i1[0]=c0.x; i1[1]=c0.y; i1[2]=c1.x; i1[3]=c1.y; i1[4]=c2.x; i1[5]=c2.y;
            float2 d0 = *(const float2*)(s2 + p0);
            float2 d1 = *(const float2*)(s2 + p1);
            float2 d2 = *(const float2*)(s2 + p2);
            i2[0]=d0.x; i2[1]=d0.y; i2[2]=d1.x; i2[3]=d1.y; i2[4]=d2.x; i2[5]=d2.y;
        }

        // ---- weights + accumulation ----
        #pragma unroll
        for (int tt = 0; tt < TT; ++tt) {
            #pragma unroll
            for (int dt = 0; dt < 5; ++dt) {
                const int l = tt + dt;
                float psum = PnL[l] + Pc[tt];
                float e = fmaf(2.0f, dotv[tt][dt], -psum);
                e = (fz[tt][dt] > 0.0f) ? -350.0f : e;
                float wgt;
                asm("ex2.approx.f32 %0, %1;" : "=f"(wgt) : "f"(e));
                den[tt]  += wgt;
                num0[tt] = fmaf(wgt, i0[l], num0[tt]);
                num1[tt] = fmaf(wgt, i1[l], num1[tt]);
                num2[tt] = fmaf(wgt, i2[l], num2[tt]);
            }
        }

        if (++dx == 7) { dx = 0; ++dy; }
    }

    // ---------------- cross-group reduction through smem -----------------
    __syncthreads();   // everyone done reading the tile
    if (og) {
        int p = lt * 9;                 // stride 9: conflict-light
        sm[p + 0] = num0[0]; sm[p + 1] = num0[1];
        sm[p + 2] = num1[0]; sm[p + 3] = num1[1];
        sm[p + 4] = num2[0]; sm[p + 5] = num2[1];
        sm[p + 6] = den[0];  sm[p + 7] = den[1];
    }
    __syncthreads();

    // ---------------- write out (group A only) ----------------
    if (!og) {
        int p = lt * 9;
        num0[0] += sm[p + 0]; num0[1] += sm[p + 1];
        num1[0] += sm[p + 2]; num1[1] += sm[p + 3];
        num2[0] += sm[p + 4]; num2[1] += sm[p + 5];
        den[0]  += sm[p + 6]; den[1]  += sm[p + 7];

        const int hh = h0 + ty;
        const int ww = w0 + tx;
        #pragma unroll
        for (int tt = 0; tt < TT; ++tt) {
            int t = t0 + tgb + tt;
            float inv = 1.0f / den[tt];
            int base = (hh * W + ww) * T + t;
            out[base]            = num0[tt] * inv;
            out[HWT + base]      = num1[tt] * inv;
            out[2 * HWT + base]  = num2[tt] * inv;
        }
    }
}

extern "C" void kernel_launch(void* const* d_in, const int* in_sizes, int n_in,
                              void* d_out, int out_size)
{
    const float* images   = (const float*)d_in[0];
    const float* guidance = (const float*)d_in[1];
    const float* estim    = (const float*)d_in[2];
    const float* var      = (const float*)d_in[3];
    const float* sig      = (const float*)d_in[4];
    const int*   spp      = (const int*)d_in[5];
    float* out = (float*)d_out;

    cudaFuncSetAttribute(denoise_kernel,
                         cudaFuncAttributeMaxDynamicSharedMemorySize,
                         SMEM_FLOATS * (int)sizeof(float));

    dim3 grid(W / OW, H / OH, T / OT);   // 32 x 32 x 4
    denoise_kernel<<<grid, NTHREADS, SMEM_FLOATS * sizeof(float)>>>(
        images, guidance, estim, var, sig, spp, out);
}

// round 10
// speedup vs baseline: 1.1527x; 1.1527x over previous
#include <cuda_runtime.h>
#include <math.h>

#define H 256
#define W 256
#define T 48
#define HWT (H*W*T)

// Output tile per block
#define OH 8
#define OW 8
#define OT 12
#define TT 2            // t-outputs per thread (register blocking)
#define NTHREADS 768    // 2 offset-groups x (8 tx * 8 ty * 6 tg)

// Halo'ed SMEM tile
#define HY 14           // OH + 6
#define HX 14           // OW + 6
#define HT 16           // OT + 4
#define ROWS (HY*HX)    // 196
#define PLANE (ROWS*HT) // 3136
#define NCH 18          // 9 scaled-guidance + 3 estimands + 3 variance + 3 images
#define SMEM_FLOATS (NCH*PLANE)   // 56448 floats -> 225792 bytes
#define SMEM_PAIRS (SMEM_FLOATS/2)

#define NL (TT + 4)     // 6 t-lanes loaded per row

// even rotation: keeps (jj, jj+1) pairs 8B-aligned & contiguous, and gives
// per-phase (16-lane) bank-conflict freedom for LDS.64
#define PHI2(x, y) (((((x) >> 1) & 3) + (((y) & 1) << 2)) << 1)

__global__ __launch_bounds__(NTHREADS, 1)
void denoise_kernel(const float* __restrict__ images,
                    const float* __restrict__ guidance,
                    const float* __restrict__ estimands,
                    const float* __restrict__ variance,
                    const float* __restrict__ sigma_inv,
                    const int*   __restrict__ spp_ptr,
                    float* __restrict__ out)
{
    extern __shared__ float sm[];
    __shared__ float ssig[9];   // sqrt(sigma_inv[c] * log2(e))

    const int tid = threadIdx.x;
    const int w0 = blockIdx.x * OW;
    const int h0 = blockIdx.y * OH;
    const int t0 = blockIdx.z * OT;

    if (tid < 9) {
        ssig[tid] = sqrtf(__fmul_rn(sigma_inv[tid], 1.4426950408889634f));
    }
    const float sppf = (float)spp_ptr[0];
    const float T2f  = (float)(2.8070337683438042 * 2.8070337683438042);
    __syncthreads();

    // ---------------- cooperative fill of halo'ed tile (paired) ----------
    // guidance stored PRE-SCALED: a_c = g_c * sqrt(sigma_c * log2e)
    // estimands / variance / images stored RAW (z-test must be bit-exact).
    #pragma unroll 4
    for (int it = 0; it < (SMEM_PAIRS + NTHREADS - 1) / NTHREADS; ++it) {  // 37 iters
        int idx = tid + it * NTHREADS;
        if (idx < SMEM_PAIRS) {
            int jp  = idx & 7;           // pair index in row
            int j   = jp << 1;           // even t slot (pre-rotation)
            int rid = idx >> 3;          // (c, y, x)
            int c   = rid / ROWS;
            int yx  = rid - c * ROWS;
            int y   = yx / HX;
            int x   = yx - y * HX;
            int hg = h0 + y - 3;
            int wg = w0 + x - 3;
            int tg_ = t0 + j - 2;        // even
            bool inb = ((unsigned)hg < H) & ((unsigned)wg < W) & ((unsigned)tg_ < T);
            int gidx = (hg * W + wg) * T + tg_;
            float2 val;
            if (c < 9) {
                if (inb) {
                    float2 g = *(const float2*)(guidance + c * HWT + gidx);
                    val.x = g.x * ssig[c]; val.y = g.y * ssig[c];
                } else { val.x = 0.f; val.y = 0.f; }
            } else if (c < 12) {
                if (inb) val = *(const float2*)(estimands + (c - 9) * HWT + gidx);
                else     { val.x = -2.f; val.y = -2.f; }
            } else if (c < 15) {
                if (inb) val = *(const float2*)(variance + (c - 12) * HWT + gidx);
                else     { val.x = 0.f; val.y = 0.f; }
            } else {
                if (inb) val = *(const float2*)(images + (c - 15) * HWT + gidx);
                else     { val.x = 0.f; val.y = 0.f; }
            }
            int slot = (j + PHI2(x, y)) & 15;    // even -> 8B aligned
            *(float2*)(sm + c * PLANE + (y * HX + x) * HT + slot) = val;
        }
    }
    __syncthreads();

    // ---------------- per-thread decomposition ----------------
    const int og  = (tid >= 384) ? 1 : 0;
    const int lt  = tid - og * 384;
    const int tg  = lt >> 6;          // 0..5
    const int rr  = lt & 63;
    const int ty  = rr >> 3;
    const int tx  = rr & 7;
    const int tgb = tg * TT;          // even
    const int o0  = og ? 25 : 0;      // spatial-offset range [o0, o1)
    const int o1  = og ? 49 : 25;

    // center values held in registers
    float gc[9][TT], ec[3][TT], vc[3][TT], Pc[TT];
    {
        int yc = ty + 3, xc = tx + 3;
        int ph = PHI2(xc, yc);
        int rowoff = (yc * HX + xc) * HT;
        #pragma unroll
        for (int tt = 0; tt < TT; ++tt) {
            int sl = rowoff + ((tgb + tt + 2 + ph) & 15);
            float p = 0.0f;
            #pragma unroll
            for (int c = 0; c < 9; ++c) {
                float a = sm[c * PLANE + sl];
                gc[c][tt] = a;
                p = fmaf(a, a, p);           // same chain order as P_j below
            }
            Pc[tt] = p;
            #pragma unroll
            for (int c = 0; c < 3; ++c) ec[c][tt] = sm[(9 + c) * PLANE + sl];
            #pragma unroll
            for (int c = 0; c < 3; ++c) vc[c][tt] = sm[(12 + c) * PLANE + sl];
        }
    }

    float num0[TT], num1[TT], num2[TT], den[TT];
    #pragma unroll
    for (int tt = 0; tt < TT; ++tt) { num0[tt] = 0.f; num1[tt] = 0.f; num2[tt] = 0.f; den[tt] = 0.f; }

    // ---------------- main loop over this group's spatial offsets --------
    int dy = o0 / 7, dx = o0 - 7 * (o0 / 7);
    #pragma unroll 1
    for (int o = o0; o < o1; ++o) {
        int y = ty + dy;
        int x = tx + dx;
        int rowoff = (y * HX + x) * HT;
        int ph = PHI2(x, y);
        // three even pair bases, contiguous 8B each (wrap never splits a pair)
        int p0 = rowoff + ((tgb + 0 + ph) & 15);
        int p1 = rowoff + ((tgb + 2 + ph) & 15);
        int p2 = rowoff + ((tgb + 4 + ph) & 15);

        // ---- z-test FIRST (EXACT reference rn op order per operand) ----
        // fail iff (d*d)*spp > T2*(vn+vc) for ANY channel
        int f[TT][5];
        #pragma unroll
        for (int tt = 0; tt < TT; ++tt)
            #pragma unroll
            for (int dt = 0; dt < 5; ++dt) f[tt][dt] = 0;

        #pragma unroll
        for (int c = 0; c < 3; ++c) {
            const float* se = sm + (9 + c)  * PLANE;
            const float* sv = sm + (12 + c) * PLANE;
            float2 e0 = *(const float2*)(se + p0);
            float2 e1 = *(const float2*)(se + p1);
            float2 e2 = *(const float2*)(se + p2);
            float2 v0 = *(const float2*)(sv + p0);
            float2 v1 = *(const float2*)(sv + p1);
            float2 v2 = *(const float2*)(sv + p2);
            float er[NL] = { e0.x, e0.y, e1.x, e1.y, e2.x, e2.y };
            float vr[NL] = { v0.x, v0.y, v1.x, v1.y, v2.x, v2.y };
            #pragma unroll
            for (int tt = 0; tt < TT; ++tt) {
                #pragma unroll
                for (int dt = 0; dt < 5; ++dt) {
                    const int l = tt + dt;
                    float d = __fsub_rn(er[l], ec[c][tt]);
                    float lv = __fmul_rn(__fmul_rn(d, d), sppf);
                    float rv = __fmul_rn(T2f, __fadd_rn(vr[l], vc[c][tt]));
                    f[tt][dt] |= (lv > rv);
                }
            }
        }

        int allfail = f[0][0] & f[0][1] & f[0][2] & f[0][3] & f[0][4]
                    & f[1][0] & f[1][1] & f[1][2] & f[1][3] & f[1][4];

        // Skipped taps would contribute weight ex2(-350) == +0 exactly, so
        // skipping the whole block when every tap fails is bit-identical.
        if (!allfail) {
            // guidance: dot products + on-the-fly neighbor norms
            float Pn[NL];
            float dot[TT][5];
            #pragma unroll
            for (int jj = 0; jj < NL; ++jj) Pn[jj] = 0.f;
            #pragma unroll
            for (int tt = 0; tt < TT; ++tt)
                #pragma unroll
                for (int dt = 0; dt < 5; ++dt) dot[tt][dt] = 0.f;

            #pragma unroll
            for (int c = 0; c < 9; ++c) {
                const float* sc = sm + c * PLANE;
                float2 r0 = *(const float2*)(sc + p0);
                float2 r1 = *(const float2*)(sc + p1);
                float2 r2 = *(const float2*)(sc + p2);
                float row[NL] = { r0.x, r0.y, r1.x, r1.y, r2.x, r2.y };
                #pragma unroll
                for (int jj = 0; jj < NL; ++jj) Pn[jj] = fmaf(row[jj], row[jj], Pn[jj]);
                #pragma unroll
                for (int tt = 0; tt < TT; ++tt)
                    #pragma unroll
                    for (int dt = 0; dt < 5; ++dt)
                        dot[tt][dt] = fmaf(row[tt + dt], gc[c][tt], dot[tt][dt]);
            }

            // image lanes
            float i0[NL], i1[NL], i2[NL];
            {
                const float* s0 = sm + 15 * PLANE;
                const float* s1 = sm + 16 * PLANE;
                const float* s2 = sm + 17 * PLANE;
                float2 a0 = *(const float2*)(s0 + p0);
                float2 a1 = *(const float2*)(s0 + p1);
                float2 a2 = *(const float2*)(s0 + p2);
                i0[0]=a0.x; i0[1]=a0.y; i0[2]=a1.x; i0[3]=a1.y; i0[4]=a2.x; i0[5]=a2.y;
                float2 b0 = *(const float2*)(s1 + p0);
                float2 b1 = *(const float2*)(s1 + p1);
                float2 b2 = *(const float2*)(s1 + p2);
                i1[0]=b0.x; i1[1]=b0.y; i1[2]=b1.x; i1[3]=b1.y; i1[4]=b2.x; i1[5]=b2.y;
                float2 c0 = *(const float2*)(s2 + p0);
                float2 c1 = *(const float2*)(s2 + p1);
                float2 c2 = *(const float2*)(s2 + p2);
                i2[0]=c0.x; i2[1]=c0.y; i2[2]=c1.x; i2[3]=c1.y; i2[4]=c2.x; i2[5]=c2.y;
            }

            // weights + accumulation
            #pragma unroll
            for (int tt = 0; tt < TT; ++tt) {
                #pragma unroll
                for (int dt = 0; dt < 5; ++dt) {
                    const int l = tt + dt;
                    // exp2 argument: 2*dot - Pn - Pc
                    float psum = Pn[l] + Pc[tt];
                    float e = fmaf(2.0f, dot[tt][dt], -psum);
                    e = f[tt][dt] ? -350.0f : e;     // fail -> weight == +0
                    float wgt;
                    asm("ex2.approx.f32 %0, %1;" : "=f"(wgt) : "f"(e));
                    den[tt]  += wgt;
                    num0[tt] = fmaf(wgt, i0[l], num0[tt]);
                    num1[tt] = fmaf(wgt, i1[l], num1[tt]);
                    num2[tt] = fmaf(wgt, i2[l], num2[tt]);
                }
            }
        }

        if (++dx == 7) { dx = 0; ++dy; }
    }

    // ---------------- cross-group reduction through smem -----------------
    __syncthreads();   // everyone done reading the tile
    if (og) {
        int p = lt * 9;                 // stride 9: conflict-light
        sm[p + 0] = num0[0]; sm[p + 1] = num0[1];
        sm[p + 2] = num1[0]; sm[p + 3] = num1[1];
        sm[p + 4] = num2[0]; sm[p + 5] = num2[1];
        sm[p + 6] = den[0];  sm[p + 7] = den[1];
    }
    __syncthreads();

    // ---------------- write out (group A only) ----------------
    if (!og) {
        int p = lt * 9;
        num0[0] += sm[p + 0]; num0[1] += sm[p + 1];
        num1[0] += sm[p + 2]; num1[1] += sm[p + 3];
        num2[0] += sm[p + 4]; num2[1] += sm[p + 5];
        den[0]  += sm[p + 6]; den[1]  += sm[p + 7];

        const int hh = h0 + ty;
        const int ww = w0 + tx;
        #pragma unroll
        for (int tt = 0; tt < TT; ++tt) {
            int t = t0 + tgb + tt;
            float inv = 1.0f / den[tt];
            int base = (hh * W + ww) * T + t;
            out[base]            = num0[tt] * inv;
            out[HWT + base]      = num1[tt] * inv;
            out[2 * HWT + base]  = num2[tt] * inv;
        }
    }
}

extern "C" void kernel_launch(void* const* d_in, const int* in_sizes, int n_in,
                              void* d_out, int out_size)
{
    const float* images   = (const float*)d_in[0];
    const float* guidance = (const float*)d_in[1];
    const float* estim    = (const float*)d_in[2];
    const float* var      = (const float*)d_in[3];
    const float* sig      = (const float*)d_in[4];
    const int*   spp      = (const int*)d_in[5];
    float* out = (float*)d_out;

    cudaFuncSetAttribute(denoise_kernel,
                         cudaFuncAttributeMaxDynamicSharedMemorySize,
                         SMEM_FLOATS * (int)sizeof(float));

    dim3 grid(W / OW, H / OH, T / OT);   // 32 x 32 x 4
    denoise_kernel<<<grid, NTHREADS, SMEM_FLOATS * sizeof(float)>>>(
        images, guidance, estim, var, sig, spp, out);
}

// round 11
// speedup vs baseline: 1.2038x; 1.0444x over previous
#include <cuda_runtime.h>
#include <math.h>

#define H 256
#define W 256
#define T 48
#define HWT (H*W*T)

// Output tile per block
#define OH 8
#define OW 8
#define OT 12
#define TT 2            // t-outputs per thread (register blocking)
#define NTHREADS 768    // 2 offset-groups x (8 tx * 8 ty * 6 tg)

// Halo'ed SMEM tile
#define HY 14           // OH + 6
#define HX 14           // OW + 6
#define HT 16           // OT + 4
#define ROWS (HY*HX)    // 196
#define PLANE (ROWS*HT) // 3136
#define NCH 18          // 9 scaled-guidance + 3 estimands + 3 variance + 3 images
#define SMEM_FLOATS (NCH*PLANE)   // 56448 floats -> 225792 bytes
#define SMEM_PAIRS (SMEM_FLOATS/2)

#define NL (TT + 4)     // 6 t-lanes loaded per row

// even rotation: keeps (jj, jj+1) pairs 8B-aligned & contiguous, and gives
// per-phase (16-lane) bank-conflict freedom for LDS.64
#define PHI2(x, y) (((((x) >> 1) & 3) + (((y) & 1) << 2)) << 1)

__global__ __launch_bounds__(NTHREADS, 1)
void denoise_kernel(const float* __restrict__ images,
                    const float* __restrict__ guidance,
                    const float* __restrict__ estimands,
                    const float* __restrict__ variance,
                    const float* __restrict__ sigma_inv,
                    const int*   __restrict__ spp_ptr,
                    float* __restrict__ out)
{
    extern __shared__ float sm[];
    __shared__ float ssig[9];   // sqrt(sigma_inv[c] * log2(e))

    const int tid = threadIdx.x;
    const int w0 = blockIdx.x * OW;
    const int h0 = blockIdx.y * OH;
    const int t0 = blockIdx.z * OT;

    if (tid < 9) {
        ssig[tid] = sqrtf(__fmul_rn(sigma_inv[tid], 1.4426950408889634f));
    }
    const float sppf = (float)spp_ptr[0];
    const float T2f  = (float)(2.8070337683438042 * 2.8070337683438042);
    // spp is a power of two (64): dividing both comparison sides by spp is
    // EXACT and commutes with rn rounding, so the test
    //   rnd(rnd(d^2)*spp) > rnd(T2*s)   <=>   rnd(d^2) > rnd((T2/spp)*s)
    // is bit-identical to the reference while saving one FMUL per operand.
    const float T2d  = T2f / sppf;
    __syncthreads();

    // ---------------- cooperative fill of halo'ed tile (paired) ----------
    // guidance stored PRE-SCALED: a_c = g_c * sqrt(sigma_c * log2e)
    // estimands / variance / images stored RAW (z-test must be bit-exact).
    #pragma unroll 4
    for (int it = 0; it < (SMEM_PAIRS + NTHREADS - 1) / NTHREADS; ++it) {  // 37 iters
        int idx = tid + it * NTHREADS;
        if (idx < SMEM_PAIRS) {
            int jp  = idx & 7;           // pair index in row
            int j   = jp << 1;           // even t slot (pre-rotation)
            int rid = idx >> 3;          // (c, y, x)
            int c   = rid / ROWS;
            int yx  = rid - c * ROWS;
            int y   = yx / HX;
            int x   = yx - y * HX;
            int hg = h0 + y - 3;
            int wg = w0 + x - 3;
            int tg_ = t0 + j - 2;        // even
            bool inb = ((unsigned)hg < H) & ((unsigned)wg < W) & ((unsigned)tg_ < T);
            int gidx = (hg * W + wg) * T + tg_;
            float2 val;
            if (c < 9) {
                if (inb) {
                    float2 g = *(const float2*)(guidance + c * HWT + gidx);
                    val.x = g.x * ssig[c]; val.y = g.y * ssig[c];
                } else { val.x = 0.f; val.y = 0.f; }
            } else if (c < 12) {
                if (inb) val = *(const float2*)(estimands + (c - 9) * HWT + gidx);
                else     { val.x = -2.f; val.y = -2.f; }
            } else if (c < 15) {
                if (inb) val = *(const float2*)(variance + (c - 12) * HWT + gidx);
                else     { val.x = 0.f; val.y = 0.f; }
            } else {
                if (inb) val = *(const float2*)(images + (c - 15) * HWT + gidx);
                else     { val.x = 0.f; val.y = 0.f; }
            }
            int slot = (j + PHI2(x, y)) & 15;    // even -> 8B aligned
            *(float2*)(sm + c * PLANE + (y * HX + x) * HT + slot) = val;
        }
    }
    __syncthreads();

    // ---------------- per-thread decomposition ----------------
    const int og  = (tid >= 384) ? 1 : 0;
    const int lt  = tid - og * 384;
    const int tg  = lt >> 6;          // 0..5
    const int rr  = lt & 63;
    const int ty  = rr >> 3;
    const int tx  = rr & 7;
    const int tgb = tg * TT;          // even
    const int o0  = og ? 25 : 0;      // spatial-offset range [o0, o1)
    const int o1  = og ? 49 : 25;

    // center values held in registers
    float gc[9][TT], ec[3][TT], vc[3][TT], Pc[TT];
    {
        int yc = ty + 3, xc = tx + 3;
        int ph = PHI2(xc, yc);
        int rowoff = (yc * HX + xc) * HT;
        #pragma unroll
        for (int tt = 0; tt < TT; ++tt) {
            int sl = rowoff + ((tgb + tt + 2 + ph) & 15);
            float p = 0.0f;
            #pragma unroll
            for (int c = 0; c < 9; ++c) {
                float a = sm[c * PLANE + sl];
                gc[c][tt] = a;
                p = fmaf(a, a, p);           // same chain order as P_j below
            }
            Pc[tt] = p;
            #pragma unroll
            for (int c = 0; c < 3; ++c) ec[c][tt] = sm[(9 + c) * PLANE + sl];
            #pragma unroll
            for (int c = 0; c < 3; ++c) vc[c][tt] = sm[(12 + c) * PLANE + sl];
        }
    }

    float num0[TT], num1[TT], num2[TT], den[TT];
    #pragma unroll
    for (int tt = 0; tt < TT; ++tt) { num0[tt] = 0.f; num1[tt] = 0.f; num2[tt] = 0.f; den[tt] = 0.f; }

    // ---------------- main loop over this group's spatial offsets --------
    int dy = o0 / 7, dx = o0 - 7 * (o0 / 7);
    #pragma unroll 1
    for (int o = o0; o < o1; ++o) {
        int y = ty + dy;
        int x = tx + dx;
        int rowoff = (y * HX + x) * HT;
        int ph = PHI2(x, y);
        // three even pair bases, contiguous 8B each (wrap never splits a pair)
        int p0 = rowoff + ((tgb + 0 + ph) & 15);
        int p1 = rowoff + ((tgb + 2 + ph) & 15);
        int p2 = rowoff + ((tgb + 4 + ph) & 15);

        // ---- z-test FIRST (bit-exact: pow2-spp folded into T2d) ----
        // fail iff rnd(d^2) > rnd(T2d*(vn+vc))  [== reference decision]
        int f[TT][5];
        #pragma unroll
        for (int tt = 0; tt < TT; ++tt)
            #pragma unroll
            for (int dt = 0; dt < 5; ++dt) f[tt][dt] = 0;

        #pragma unroll
        for (int c = 0; c < 3; ++c) {
            const float* se = sm + (9 + c)  * PLANE;
            const float* sv = sm + (12 + c) * PLANE;
            float2 e0 = *(const float2*)(se + p0);
            float2 e1 = *(const float2*)(se + p1);
            float2 e2 = *(const float2*)(se + p2);
            float2 v0 = *(const float2*)(sv + p0);
            float2 v1 = *(const float2*)(sv + p1);
            float2 v2 = *(const float2*)(sv + p2);
            float er[NL] = { e0.x, e0.y, e1.x, e1.y, e2.x, e2.y };
            float vr[NL] = { v0.x, v0.y, v1.x, v1.y, v2.x, v2.y };
            #pragma unroll
            for (int tt = 0; tt < TT; ++tt) {
                #pragma unroll
                for (int dt = 0; dt < 5; ++dt) {
                    const int l = tt + dt;
                    float d = __fsub_rn(er[l], ec[c][tt]);
                    float q = __fmul_rn(d, d);
                    float rv = __fmul_rn(T2d, __fadd_rn(vr[l], vc[c][tt]));
                    f[tt][dt] |= (q > rv);
                }
            }
        }

        int allfail = f[0][0] & f[0][1] & f[0][2] & f[0][3] & f[0][4]
                    & f[1][0] & f[1][1] & f[1][2] & f[1][3] & f[1][4];

        // Skipped taps would contribute weight ex2(-350) == +0 exactly, so
        // skipping the whole block when every tap fails is bit-identical.
        if (!allfail) {
            // guidance: dot products + on-the-fly neighbor norms
            float Pn[NL];
            float dot[TT][5];
            #pragma unroll
            for (int jj = 0; jj < NL; ++jj) Pn[jj] = 0.f;
            #pragma unroll
            for (int tt = 0; tt < TT; ++tt)
                #pragma unroll
                for (int dt = 0; dt < 5; ++dt) dot[tt][dt] = 0.f;

            #pragma unroll
            for (int c = 0; c < 9; ++c) {
                const float* sc = sm + c * PLANE;
                float2 r0 = *(const float2*)(sc + p0);
                float2 r1 = *(const float2*)(sc + p1);
                float2 r2 = *(const float2*)(sc + p2);
                float row[NL] = { r0.x, r0.y, r1.x, r1.y, r2.x, r2.y };
                #pragma unroll
                for (int jj = 0; jj < NL; ++jj) Pn[jj] = fmaf(row[jj], row[jj], Pn[jj]);
                #pragma unroll
                for (int tt = 0; tt < TT; ++tt)
                    #pragma unroll
                    for (int dt = 0; dt < 5; ++dt)
                        dot[tt][dt] = fmaf(row[tt + dt], gc[c][tt], dot[tt][dt]);
            }

            // image lanes
            float i0[NL], i1[NL], i2[NL];
            {
                const float* s0 = sm + 15 * PLANE;
                const float* s1 = sm + 16 * PLANE;
                const float* s2 = sm + 17 * PLANE;
                float2 a0 = *(const float2*)(s0 + p0);
                float2 a1 = *(const float2*)(s0 + p1);
                float2 a2 = *(const float2*)(s0 + p2);
                i0[0]=a0.x; i0[1]=a0.y; i0[2]=a1.x; i0[3]=a1.y; i0[4]=a2.x; i0[5]=a2.y;
                float2 b0 = *(const float2*)(s1 + p0);
                float2 b1 = *(const float2*)(s1 + p1);
                float2 b2 = *(const float2*)(s1 + p2);
                i1[0]=b0.x; i1[1]=b0.y; i1[2]=b1.x; i1[3]=b1.y; i1[4]=b2.x; i1[5]=b2.y;
                float2 c0 = *(const float2*)(s2 + p0);
                float2 c1 = *(const float2*)(s2 + p1);
                float2 c2 = *(const float2*)(s2 + p2);
                i2[0]=c0.x; i2[1]=c0.y; i2[2]=c1.x; i2[3]=c1.y; i2[4]=c2.x; i2[5]=c2.y;
            }

            // weights + accumulation
            #pragma unroll
            for (int tt = 0; tt < TT; ++tt) {
                #pragma unroll
                for (int dt = 0; dt < 5; ++dt) {
                    const int l = tt + dt;
                    // exp2 argument: 2*dot - Pn - Pc
                    float psum = Pn[l] + Pc[tt];
                    float e = fmaf(2.0f, dot[tt][dt], -psum);
                    e = f[tt][dt] ? -350.0f : e;     // fail -> weight == +0
                    float wgt;
                    asm("ex2.approx.f32 %0, %1;" : "=f"(wgt) : "f"(e));
                    den[tt]  += wgt;
                    num0[tt] = fmaf(wgt, i0[l], num0[tt]);
                    num1[tt] = fmaf(wgt, i1[l], num1[tt]);
                    num2[tt] = fmaf(wgt, i2[l], num2[tt]);
                }
            }
        }

        if (++dx == 7) { dx = 0; ++dy; }
    }

    // ---------------- cross-group reduction through smem -----------------
    __syncthreads();   // everyone done reading the tile
    if (og) {
        int p = lt * 9;                 // stride 9: conflict-light
        sm[p + 0] = num0[0]; sm[p + 1] = num0[1];
        sm[p + 2] = num1[0]; sm[p + 3] = num1[1];
        sm[p + 4] = num2[0]; sm[p + 5] = num2[1];
        sm[p + 6] = den[0];  sm[p + 7] = den[1];
    }
    __syncthreads();

    // ---------------- write out (group A only) ----------------
    if (!og) {
        int p = lt * 9;
        num0[0] += sm[p + 0]; num0[1] += sm[p + 1];
        num1[0] += sm[p + 2]; num1[1] += sm[p + 3];
        num2[0] += sm[p + 4]; num2[1] += sm[p + 5];
        den[0]  += sm[p + 6]; den[1]  += sm[p + 7];

        const int hh = h0 + ty;
        const int ww = w0 + tx;
        #pragma unroll
        for (int tt = 0; tt < TT; ++tt) {
            int t = t0 + tgb + tt;
            float inv = 1.0f / den[tt];
            int base = (hh * W + ww) * T + t;
            out[base]            = num0[tt] * inv;
            out[HWT + base]      = num1[tt] * inv;
            out[2 * HWT + base]  = num2[tt] * inv;
        }
    }
}

extern "C" void kernel_launch(void* const* d_in, const int* in_sizes, int n_in,
                              void* d_out, int out_size)
{
    const float* images   = (const float*)d_in[0];
    const float* guidance = (const float*)d_in[1];
    const float* estim    = (const float*)d_in[2];
    const float* var      = (const float*)d_in[3];
    const float* sig      = (const float*)d_in[4];
    const int*   spp      = (const int*)d_in[5];
    float* out = (float*)d_out;

    cudaFuncSetAttribute(denoise_kernel,
                         cudaFuncAttributeMaxDynamicSharedMemorySize,
                         SMEM_FLOATS * (int)sizeof(float));

    dim3 grid(W / OW, H / OH, T / OT);   // 32 x 32 x 4
    denoise_kernel<<<grid, NTHREADS, SMEM_FLOATS * sizeof(float)>>>(
        images, guidance, estim, var, sig, spp, out);
}

// round 13
// speedup vs baseline: 1.5166x; 1.2598x over previous
#include <cuda_runtime.h>
#include <math.h>

#define H 256
#define W 256
#define T 48
#define HWT (H*W*T)

// Output tile per block
#define OH 8
#define OW 4
#define OT 12
#define TT 2            // t-outputs per thread (register blocking)
#define NOG 4           // offset groups
#define NTHREADS 768    // 4 og x (6 tg x 8 ty x 4 tx)

// Halo'ed SMEM tile
#define HY 14           // OH + 6
#define HX 10           // OW + 6
#define HT 16           // OT + 4
#define ROWS (HY*HX)    // 140
#define PLANE (ROWS*HT) // 2240
#define NCH 19          // 9 scaled-guidance + 3 est + 3 var + 3 img + 1 P
#define SMEM_FLOATS (NCH*PLANE)   // 42560 floats -> 170240 bytes
#define NPOS (ROWS*8)   // 1120 pair-positions per channel-plane

#define NL (TT + 4)     // 6 t-lanes loaded per row

// even rotation for warp shape 8ty x 4tx (16-lane phase = 4ty x 4tx):
// 8B-bank = 8*(x&1) + ((K + ((x>>1)&1) + 2*(y&3)) & 7)  -> all 16 distinct
#define PHI2(x, y) (((((x) >> 1) & 1) + (((y) & 3) << 1)) << 1)

__global__ __launch_bounds__(NTHREADS, 1)
void denoise_kernel(const float* __restrict__ images,
                    const float* __restrict__ guidance,
                    const float* __restrict__ estimands,
                    const float* __restrict__ variance,
                    const float* __restrict__ sigma_inv,
                    const int*   __restrict__ spp_ptr,
                    float* __restrict__ out)
{
    extern __shared__ float sm[];
    __shared__ float ssig[9];   // sqrt(sigma_inv[c] * log2(e))

    const int tid = threadIdx.x;
    const int w0 = blockIdx.x * OW;
    const int h0 = blockIdx.y * OH;
    const int t0 = blockIdx.z * OT;

    if (tid < 9) {
        ssig[tid] = sqrtf(__fmul_rn(sigma_inv[tid], 1.4426950408889634f));
    }
    const float sppf = (float)spp_ptr[0];
    const float T2f  = (float)(2.8070337683438042 * 2.8070337683438042);
    // spp is a power of two (64): dividing both sides by spp is EXACT, so
    //   rnd(rnd(d^2)*spp) > rnd(T2*s)  <=>  rnd(d^2) > rnd((T2/spp)*s)
    const float T2d  = T2f / sppf;
    __syncthreads();

    // ---------------- cooperative fill: per-position, channels hoisted ---
    // One thread handles one (y,x,t-pair) position for ALL 19 channels:
    // index math / bounds / gidx computed once. P (channel 18) accumulated
    // from the scaled guidance with the SAME ascending-c fmaf chain as the
    // main-loop dot (center cancellation stays exact).
    for (int pos = tid; pos < NPOS; pos += NTHREADS) {
        int jp    = pos & 7;
        int rowid = pos >> 3;
        int y  = rowid / HX;
        int x  = rowid - y * HX;
        int hg = h0 + y - 3;
        int wg = w0 + x - 3;
        int tg_ = t0 + (jp << 1) - 2;    // even
        bool inb = ((unsigned)hg < H) & ((unsigned)wg < W) & ((unsigned)tg_ < T);
        int gidx = (hg * W + wg) * T + tg_;
        int slot = ((jp << 1) + PHI2(x, y)) & 15;   // even -> 8B aligned
        float* dst = sm + rowid * HT + slot;

        float2 P2; P2.x = 0.f; P2.y = 0.f;
        #pragma unroll
        for (int c = 0; c < 9; ++c) {
            float2 v; v.x = 0.f; v.y = 0.f;
            if (inb) {
                float2 g = *(const float2*)(guidance + c * HWT + gidx);
                v.x = g.x * ssig[c]; v.y = g.y * ssig[c];
            }
            *(float2*)(dst + c * PLANE) = v;
            P2.x = fmaf(v.x, v.x, P2.x);
            P2.y = fmaf(v.y, v.y, P2.y);
        }
        #pragma unroll
        for (int c = 0; c < 3; ++c) {
            float2 v; v.x = -2.f; v.y = -2.f;     // estimand pad
            if (inb) v = *(const float2*)(estimands + c * HWT + gidx);
            *(float2*)(dst + (9 + c) * PLANE) = v;
        }
        #pragma unroll
        for (int c = 0; c < 3; ++c) {
            float2 v; v.x = 0.f; v.y = 0.f;
            if (inb) v = *(const float2*)(variance + c * HWT + gidx);
            *(float2*)(dst + (12 + c) * PLANE) = v;
        }
        #pragma unroll
        for (int c = 0; c < 3; ++c) {
            float2 v; v.x = 0.f; v.y = 0.f;
            if (inb) v = *(const float2*)(images + c * HWT + gidx);
            *(float2*)(dst + (15 + c) * PLANE) = v;
        }
        *(float2*)(dst + 18 * PLANE) = P2;
    }
    __syncthreads();

    // ---------------- per-thread decomposition ----------------
    // warp = one (og, tg): 8 ty x 4 tx, fixed tg -> conflict-free LDS
    const int wg_id = tid >> 5;            // 0..23
    const int og  = wg_id / 6;             // 0..3
    const int tg  = wg_id - og * 6;        // 0..5
    const int rr  = tid & 31;
    const int ty  = rr >> 2;               // 0..7
    const int tx  = rr & 3;                // 0..3
    const int tgb = tg * TT;               // even
    const int lt  = tg * 32 + rr;          // 0..191 within og
    const int o0  = (og * 49) >> 2;        // 0,12,24,36
    const int o1  = ((og + 1) * 49) >> 2;  // 12,24,36,49

    // center values held in registers (pair loads; center lanes are an
    // aligned even pair tgb+2, tgb+3)
    float gc[9][TT], ec[3][TT], vc[3][TT], Pc[TT];
    {
        int yc = ty + 3, xc = tx + 3;
        int slc = (yc * HX + xc) * HT + ((tgb + 2 + PHI2(xc, yc)) & 15);
        #pragma unroll
        for (int c = 0; c < 9; ++c) {
            float2 g = *(const float2*)(sm + c * PLANE + slc);
            gc[c][0] = g.x; gc[c][1] = g.y;
        }
        #pragma unroll
        for (int c = 0; c < 3; ++c) {
            float2 e = *(const float2*)(sm + (9 + c) * PLANE + slc);
            ec[c][0] = e.x; ec[c][1] = e.y;
        }
        #pragma unroll
        for (int c = 0; c < 3; ++c) {
            float2 v = *(const float2*)(sm + (12 + c) * PLANE + slc);
            vc[c][0] = v.x; vc[c][1] = v.y;
        }
        float2 p = *(const float2*)(sm + 18 * PLANE + slc);
        Pc[0] = p.x; Pc[1] = p.y;
    }

    float num0[TT], num1[TT], num2[TT], den[TT];
    #pragma unroll
    for (int tt = 0; tt < TT; ++tt) { num0[tt] = 0.f; num1[tt] = 0.f; num2[tt] = 0.f; den[tt] = 0.f; }

    // ---------------- main loop over this group's spatial offsets --------
    int dy = o0 / 7, dx = o0 - 7 * (o0 / 7);
    #pragma unroll 1
    for (int o = o0; o < o1; ++o) {
        int y = ty + dy;
        int x = tx + dx;
        int rowoff = (y * HX + x) * HT;
        int ph = PHI2(x, y);
        // three even pair bases, contiguous 8B each (wrap never splits a pair)
        int p0 = rowoff + ((tgb + 0 + ph) & 15);
        int p1 = rowoff + ((tgb + 2 + ph) & 15);
        int p2 = rowoff + ((tgb + 4 + ph) & 15);

        // ---- z-test FIRST (bit-exact: pow2-spp folded into T2d) ----
        int f[TT][5];
        #pragma unroll
        for (int tt = 0; tt < TT; ++tt)
            #pragma unroll
            for (int dt = 0; dt < 5; ++dt) f[tt][dt] = 0;

        #pragma unroll
        for (int c = 0; c < 3; ++c) {
            const float* se = sm + (9 + c)  * PLANE;
            const float* sv = sm + (12 + c) * PLANE;
            float2 e0 = *(const float2*)(se + p0);
            float2 e1 = *(const float2*)(se + p1);
            float2 e2 = *(const float2*)(se + p2);
            float2 v0 = *(const float2*)(sv + p0);
            float2 v1 = *(const float2*)(sv + p1);
            float2 v2 = *(const float2*)(sv + p2);
            float er[NL] = { e0.x, e0.y, e1.x, e1.y, e2.x, e2.y };
            float vr[NL] = { v0.x, v0.y, v1.x, v1.y, v2.x, v2.y };
            #pragma unroll
            for (int tt = 0; tt < TT; ++tt) {
                #pragma unroll
                for (int dt = 0; dt < 5; ++dt) {
                    const int l = tt + dt;
                    float d = __fsub_rn(er[l], ec[c][tt]);
                    float q = __fmul_rn(d, d);
                    float rv = __fmul_rn(T2d, __fadd_rn(vr[l], vc[c][tt]));
                    f[tt][dt] |= (q > rv);
                }
            }
        }

        int allfail = f[0][0] & f[0][1] & f[0][2] & f[0][3] & f[0][4]
                    & f[1][0] & f[1][1] & f[1][2] & f[1][3] & f[1][4];

        // Skipped taps contribute weight ex2(-350) == +0 exactly.
        if (!allfail) {
            // guidance dot products (Pn now PRELOADED, not recomputed)
            float dot[TT][5];
            #pragma unroll
            for (int tt = 0; tt < TT; ++tt)
                #pragma unroll
                for (int dt = 0; dt < 5; ++dt) dot[tt][dt] = 0.f;

            #pragma unroll
            for (int c = 0; c < 9; ++c) {
                const float* sc = sm + c * PLANE;
                float2 r0 = *(const float2*)(sc + p0);
                float2 r1 = *(const float2*)(sc + p1);
                float2 r2 = *(const float2*)(sc + p2);
                float row[NL] = { r0.x, r0.y, r1.x, r1.y, r2.x, r2.y };
                #pragma unroll
                for (int tt = 0; tt < TT; ++tt)
                    #pragma unroll
                    for (int dt = 0; dt < 5; ++dt)
                        dot[tt][dt] = fmaf(row[tt + dt], gc[c][tt], dot[tt][dt]);
            }

            // neighbor norms from the precomputed P plane
            float Pn[NL];
            {
                const float* sp = sm + 18 * PLANE;
                float2 q0 = *(const float2*)(sp + p0);
                float2 q1 = *(const float2*)(sp + p1);
                float2 q2 = *(const float2*)(sp + p2);
                Pn[0]=q0.x; Pn[1]=q0.y; Pn[2]=q1.x; Pn[3]=q1.y; Pn[4]=q2.x; Pn[5]=q2.y;
            }

            // image lanes
            float i0[NL], i1[NL], i2[NL];
            {
                const float* s0 = sm + 15 * PLANE;
                const float* s1 = sm + 16 * PLANE;
                const float* s2 = sm + 17 * PLANE;
                float2 a0 = *(const float2*)(s0 + p0);
                float2 a1 = *(const float2*)(s0 + p1);
                float2 a2 = *(const float2*)(s0 + p2);
                i0[0]=a0.x; i0[1]=a0.y; i0[2]=a1.x; i0[3]=a1.y; i0[4]=a2.x; i0[5]=a2.y;
                float2 b0 = *(const float2*)(s1 + p0);
                float2 b1 = *(const float2*)(s1 + p1);
                float2 b2 = *(const float2*)(s1 + p2);
                i1[0]=b0.x; i1[1]=b0.y; i1[2]=b1.x; i1[3]=b1.y; i1[4]=b2.x; i1[5]=b2.y;
                float2 c0 = *(const float2*)(s2 + p0);
                float2 c1 = *(const float2*)(s2 + p1);
                float2 c2 = *(const float2*)(s2 + p2);
                i2[0]=c0.x; i2[1]=c0.y; i2[2]=c1.x; i2[3]=c1.y; i2[4]=c2.x; i2[5]=c2.y;
            }

            // weights + accumulation
            #pragma unroll
            for (int tt = 0; tt < TT; ++tt) {
                #pragma unroll
                for (int dt = 0; dt < 5; ++dt) {
                    const int l = tt + dt;
                    // exp2 argument: 2*dot - Pn - Pc
                    float psum = Pn[l] + Pc[tt];
                    float e = fmaf(2.0f, dot[tt][dt], -psum);
                    e = f[tt][dt] ? -350.0f : e;     // fail -> weight == +0
                    float wgt;
                    asm("ex2.approx.f32 %0, %1;" : "=f"(wgt) : "f"(e));
                    den[tt]  += wgt;
                    num0[tt] = fmaf(wgt, i0[l], num0[tt]);
                    num1[tt] = fmaf(wgt, i1[l], num1[tt]);
                    num2[tt] = fmaf(wgt, i2[l], num2[tt]);
                }
            }
        }

        if (++dx == 7) { dx = 0; ++dy; }
    }

    // ---------------- cross-group reduction through smem -----------------
    __syncthreads();   // everyone done reading the tile
    if (og != 0) {
        int p = ((og - 1) * 192 + lt) * 9;       // stride 9: conflict-light
        sm[p + 0] = num0[0]; sm[p + 1] = num0[1];
        sm[p + 2] = num1[0]; sm[p + 3] = num1[1];
        sm[p + 4] = num2[0]; sm[p + 5] = num2[1];
        sm[p + 6] = den[0];  sm[p + 7] = den[1];
    }
    __syncthreads();

    // ---------------- write out (group 0 only) ----------------
    if (og == 0) {
        #pragma unroll
        for (int g = 0; g < 3; ++g) {
            int p = (g * 192 + lt) * 9;
            num0[0] += sm[p + 0]; num0[1] += sm[p + 1];
            num1[0] += sm[p + 2]; num1[1] += sm[p + 3];
            num2[0] += sm[p + 4]; num2[1] += sm[p + 5];
            den[0]  += sm[p + 6]; den[1]  += sm[p + 7];
        }

        const int hh = h0 + ty;
        const int ww = w0 + tx;
        #pragma unroll
        for (int tt = 0; tt < TT; ++tt) {
            int t = t0 + tgb + tt;
            float inv = 1.0f / den[tt];
            int base = (hh * W + ww) * T + t;
            out[base]            = num0[tt] * inv;
            out[HWT + base]      = num1[tt] * inv;
            out[2 * HWT + base]  = num2[tt] * inv;
        }
    }
}

extern "C" void kernel_launch(void* const* d_in, const int* in_sizes, int n_in,
                              void* d_out, int out_size)
{
    const float* images   = (const float*)d_in[0];
    const float* guidance = (const float*)d_in[1];
    const float* estim    = (const float*)d_in[2];
    const float* var      = (const float*)d_in[3];
    const float* sig      = (const float*)d_in[4];
    const int*   spp      = (const int*)d_in[5];
    float* out = (float*)d_out;

    cudaFuncSetAttribute(denoise_kernel,
                         cudaFuncAttributeMaxDynamicSharedMemorySize,
                         SMEM_FLOATS * (int)sizeof(float));

    dim3 grid(W / OW, H / OH, T / OT);   // 64 x 32 x 4
    denoise_kernel<<<grid, NTHREADS, SMEM_FLOATS * sizeof(float)>>>(
        images, guidance, estim, var, sig, spp, out);
}

// round 15
// speedup vs baseline: 1.5207x; 1.0027x over previous
#include <cuda_runtime.h>
#include <math.h>

#define H 256
#define W 256
#define T 48
#define HWT (H*W*T)

// Output tile per block
#define OH 8
#define OW 4
#define OT 12
#define TT 2            // t-outputs per thread (register blocking)
#define NTHREADS 768    // 4 og x (6 tg x 8 ty x 4 tx)

// Halo'ed SMEM tile
#define HY 14           // OH + 6
#define HX 10           // OW + 6
#define HT 16           // t-slots per voxel
#define ROWS (HY*HX)    // 140
#define QSTRIDE 32      // quad-plane voxel stride (floats): 8 quads
#define PSTRIDE 16      // pair-plane voxel stride (floats)
#define QPLANE (ROWS*QSTRIDE)  // 4480
#define PPLANE (ROWS*PSTRIDE)  // 2240

// float offsets of the channel groups
#define OFF_G01 0                     // guidance ch0/ch1 interleaved quads
#define OFF_EV0 (4*QPLANE)            // [e,e,v,v] quads, ch0..2
#define OFF_I01 (7*QPLANE)            // image ch0/ch1 interleaved quads
#define OFF_G8  (8*QPLANE)            // guidance ch8, pair layout
#define OFF_I2  (OFF_G8 + PPLANE)     // image ch2, pair layout
#define OFF_P   (OFF_I2 + PPLANE)     // neighbor norms, pair layout
#define SMEM_FLOATS (OFF_P + PPLANE)  // 42560 floats -> 170240 bytes

#define NPOS (ROWS*8)   // 1120 (voxel, t-pair) positions

#define NL (TT + 4)     // 6 t-lanes used per row

// pair-plane rotation (16-lane phase = 4ty x 4tx): conflict-free LDS.64
#define PHI2(x, y) (((((x) >> 1) & 1) + (((y) & 3) << 1)) << 1)
// quad-plane rotation (8-lane phase = 2ty x 4tx): bank16 = quad-index, so the
// rotation must be a bijection over each phase -> conflict-free LDS.128
#define RHO8(x, y) (((((y) & 1) << 2) | ((x) & 3)))

__global__ __launch_bounds__(NTHREADS, 1)
void denoise_kernel(const float* __restrict__ images,
                    const float* __restrict__ guidance,
                    const float* __restrict__ estimands,
                    const float* __restrict__ variance,
                    const float* __restrict__ sigma_inv,
                    const int*   __restrict__ spp_ptr,
                    float* __restrict__ out)
{
    extern __shared__ float sm[];
    __shared__ float ssig[9];   // sqrt(sigma_inv[c] * log2(e))

    const int tid = threadIdx.x;
    const int w0 = blockIdx.x * OW;
    const int h0 = blockIdx.y * OH;
    const int t0 = blockIdx.z * OT;

    if (tid < 9) {
        ssig[tid] = sqrtf(__fmul_rn(sigma_inv[tid], 1.4426950408889634f));
    }
    const float sppf = (float)spp_ptr[0];
    const float T2f  = (float)(2.8070337683438042 * 2.8070337683438042);
    // spp is a power of two (64): dividing both sides by spp is EXACT, so
    //   rnd(rnd(d^2)*spp) > rnd(T2*s)  <=>  rnd(d^2) > rnd((T2/spp)*s)
    const float T2d  = T2f / sppf;
    __syncthreads();

    // ---------------- cooperative fill: per-position, channels hoisted ---
    // guidance scaled by ssig; estimands/variance RAW (bit-exact z-test);
    // P accumulated with the ascending-c fmaf chain.
    for (int pos = tid; pos < NPOS; pos += NTHREADS) {
        int jp    = pos & 7;
        int rowid = pos >> 3;
        int y  = rowid / HX;
        int x  = rowid - y * HX;
        int hg = h0 + y - 3;
        int wg = w0 + x - 3;
        int tg_ = t0 + (jp << 1) - 2;    // even
        bool inb = ((unsigned)hg < H) & ((unsigned)wg < W) & ((unsigned)tg_ < T);
        int gidx = (hg * W + wg) * T + tg_;
        int qoff = rowid * QSTRIDE + (((jp + RHO8(x, y)) & 7) << 2);
        int poff = rowid * PSTRIDE + (((jp << 1) + PHI2(x, y)) & 15);

        // guidance: load 9 scaled pairs, accumulate P, store 4 quads + 1 pair
        float2 gs[9];
        float2 P2; P2.x = 0.f; P2.y = 0.f;
        #pragma unroll
        for (int c = 0; c < 9; ++c) {
            float2 v; v.x = 0.f; v.y = 0.f;
            if (inb) {
                float2 g = *(const float2*)(guidance + c * HWT + gidx);
                v.x = g.x * ssig[c]; v.y = g.y * ssig[c];
            }
            gs[c] = v;
            P2.x = fmaf(v.x, v.x, P2.x);
            P2.y = fmaf(v.y, v.y, P2.y);
        }
        #pragma unroll
        for (int cp = 0; cp < 4; ++cp) {
            float4 q;
            q.x = gs[2*cp].x;   q.y = gs[2*cp].y;
            q.z = gs[2*cp+1].x; q.w = gs[2*cp+1].y;
            *(float4*)(sm + OFF_G01 + cp * QPLANE + qoff) = q;
        }
        *(float2*)(sm + OFF_G8 + poff) = gs[8];
        *(float2*)(sm + OFF_P  + poff) = P2;

        // estimands + variance interleaved quads
        #pragma unroll
        for (int c = 0; c < 3; ++c) {
            float2 e; e.x = -2.f; e.y = -2.f;    // estimand pad
            float2 v; v.x = 0.f;  v.y = 0.f;
            if (inb) {
                e = *(const float2*)(estimands + c * HWT + gidx);
                v = *(const float2*)(variance  + c * HWT + gidx);
            }
            float4 q; q.x = e.x; q.y = e.y; q.z = v.x; q.w = v.y;
            *(float4*)(sm + OFF_EV0 + c * QPLANE + qoff) = q;
        }

        // images: ch0/ch1 quad + ch2 pair
        {
            float2 a; a.x = 0.f; a.y = 0.f;
            float2 b; b.x = 0.f; b.y = 0.f;
            float2 cc; cc.x = 0.f; cc.y = 0.f;
            if (inb) {
                a  = *(const float2*)(images + 0 * HWT + gidx);
                b  = *(const float2*)(images + 1 * HWT + gidx);
                cc = *(const float2*)(images + 2 * HWT + gidx);
            }
            float4 q; q.x = a.x; q.y = a.y; q.z = b.x; q.w = b.y;
            *(float4*)(sm + OFF_I01 + qoff) = q;
            *(float2*)(sm + OFF_I2 + poff) = cc;
        }
    }
    __syncthreads();

    // ---------------- per-thread decomposition ----------------
    const int wg_id = tid >> 5;            // 0..23
    const int og  = wg_id / 6;             // 0..3
    const int tg  = wg_id - og * 6;        // 0..5
    const int rr  = tid & 31;
    const int ty  = rr >> 2;               // 0..7
    const int tx  = rr & 3;                // 0..3
    const int tgb = tg * TT;               // even
    const int kb  = tg;                    // t-pair base = tgb/2
    const int lt  = tg * 32 + rr;          // 0..191 within og
    const int o0  = (og * 49) >> 2;        // 0,12,24,36
    const int o1  = ((og + 1) * 49) >> 2;  // 12,24,36,49

    // center values: gc DOUBLED (exact x2) for the seeded-dot trick
    float gc2[9][TT], ec[3][TT], vc[3][TT], negPc[TT];
    {
        int xc = tx + 3, yc = ty + 3;
        int rowc = yc * HX + xc;
        int qc = rowc * QSTRIDE + (((kb + 1 + RHO8(xc, yc)) & 7) << 2);
        int pc = rowc * PSTRIDE + ((tgb + 2 + PHI2(xc, yc)) & 15);
        #pragma unroll
        for (int cp = 0; cp < 4; ++cp) {
            float4 q = *(const float4*)(sm + OFF_G01 + cp * QPLANE + qc);
            gc2[2*cp][0]   = 2.0f * q.x; gc2[2*cp][1]   = 2.0f * q.y;
            gc2[2*cp+1][0] = 2.0f * q.z; gc2[2*cp+1][1] = 2.0f * q.w;
        }
        {
            float2 g = *(const float2*)(sm + OFF_G8 + pc);
            gc2[8][0] = 2.0f * g.x; gc2[8][1] = 2.0f * g.y;
        }
        #pragma unroll
        for (int c = 0; c < 3; ++c) {
            float4 q = *(const float4*)(sm + OFF_EV0 + c * QPLANE + qc);
            ec[c][0] = q.x; ec[c][1] = q.y;
            vc[c][0] = q.z; vc[c][1] = q.w;
        }
        float2 p = *(const float2*)(sm + OFF_P + pc);
        negPc[0] = -p.x; negPc[1] = -p.y;
    }

    float num0[TT], num1[TT], num2[TT], den[TT];
    #pragma unroll
    for (int tt = 0; tt < TT; ++tt) { num0[tt] = 0.f; num1[tt] = 0.f; num2[tt] = 0.f; den[tt] = 0.f; }

    // ---------------- main loop over this group's spatial offsets --------
    int dy = o0 / 7, dx = o0 - 7 * (o0 / 7);
    #pragma unroll 1
    for (int o = o0; o < o1; ++o) {
        int y = ty + dy;
        int x = tx + dx;
        int rowid = y * HX + x;
        int rq = rowid * QSTRIDE;
        int rp = rowid * PSTRIDE;
        int r8 = RHO8(x, y);
        int q0 = rq + (((kb + 0 + r8) & 7) << 2);
        int q1 = rq + (((kb + 1 + r8) & 7) << 2);
        int q2 = rq + (((kb + 2 + r8) & 7) << 2);
        int ph = PHI2(x, y);
        int p0 = rp + ((tgb + 0 + ph) & 15);
        int p1 = rp + ((tgb + 2 + ph) & 15);
        int p2 = rp + ((tgb + 4 + ph) & 15);

        // ---- z-test FIRST (bit-exact), one LDS.128 per (channel, quad) ----
        int f[TT][5];
        #pragma unroll
        for (int tt = 0; tt < TT; ++tt)
            #pragma unroll
            for (int dt = 0; dt < 5; ++dt) f[tt][dt] = 0;

        #pragma unroll
        for (int c = 0; c < 3; ++c) {
            const float* se = sm + OFF_EV0 + c * QPLANE;
            float4 a = *(const float4*)(se + q0);
            float4 b = *(const float4*)(se + q1);
            float4 g = *(const float4*)(se + q2);
            float er[NL] = { a.x, a.y, b.x, b.y, g.x, g.y };
            float vr[NL] = { a.z, a.w, b.z, b.w, g.z, g.w };
            #pragma unroll
            for (int tt = 0; tt < TT; ++tt) {
                #pragma unroll
                for (int dt = 0; dt < 5; ++dt) {
                    const int l = tt + dt;
                    float d = __fsub_rn(er[l], ec[c][tt]);
                    float q = __fmul_rn(d, d);
                    float rv = __fmul_rn(T2d, __fadd_rn(vr[l], vc[c][tt]));
                    f[tt][dt] |= (q > rv);
                }
            }
        }

        int allfail = f[0][0] & f[0][1] & f[0][2] & f[0][3] & f[0][4]
                    & f[1][0] & f[1][1] & f[1][2] & f[1][3] & f[1][4];

        // Skipped taps contribute weight ex2(-350) == +0 exactly.
        if (!allfail) {
            // dot2 accumulators seeded with -Pc; gc2 pre-doubled, so
            // final exp2 argument = 2*dot - Pc - Pn = dot2 - Pn
            float dot2[TT][5];
            #pragma unroll
            for (int tt = 0; tt < TT; ++tt)
                #pragma unroll
                for (int dt = 0; dt < 5; ++dt) dot2[tt][dt] = negPc[tt];

            #pragma unroll
            for (int cp = 0; cp < 4; ++cp) {
                const float* sc = sm + OFF_G01 + cp * QPLANE;
                float4 u0 = *(const float4*)(sc + q0);
                float4 u1 = *(const float4*)(sc + q1);
                float4 u2 = *(const float4*)(sc + q2);
                float rowA[NL] = { u0.x, u0.y, u1.x, u1.y, u2.x, u2.y };
                float rowB[NL] = { u0.z, u0.w, u1.z, u1.w, u2.z, u2.w };
                #pragma unroll
                for (int tt = 0; tt < TT; ++tt)
                    #pragma unroll
                    for (int dt = 0; dt < 5; ++dt) {
                        dot2[tt][dt] = fmaf(rowA[tt + dt], gc2[2*cp][tt],   dot2[tt][dt]);
                        dot2[tt][dt] = fmaf(rowB[tt + dt], gc2[2*cp+1][tt], dot2[tt][dt]);
                    }
            }
            {   // channel 8 (pair plane)
                const float* sc = sm + OFF_G8;
                float2 r0 = *(const float2*)(sc + p0);
                float2 r1 = *(const float2*)(sc + p1);
                float2 r2 = *(const float2*)(sc + p2);
                float row[NL] = { r0.x, r0.y, r1.x, r1.y, r2.x, r2.y };
                #pragma unroll
                for (int tt = 0; tt < TT; ++tt)
                    #pragma unroll
                    for (int dt = 0; dt < 5; ++dt)
                        dot2[tt][dt] = fmaf(row[tt + dt], gc2[8][tt], dot2[tt][dt]);
            }

            // neighbor norms from the precomputed P plane
            float Pn[NL];
            {
                const float* sp = sm + OFF_P;
                float2 a = *(const float2*)(sp + p0);
                float2 b = *(const float2*)(sp + p1);
                float2 g = *(const float2*)(sp + p2);
                Pn[0]=a.x; Pn[1]=a.y; Pn[2]=b.x; Pn[3]=b.y; Pn[4]=g.x; Pn[5]=g.y;
            }

            // image lanes
            float i0[NL], i1[NL], i2[NL];
            {
                const float* s01 = sm + OFF_I01;
                float4 a = *(const float4*)(s01 + q0);
                float4 b = *(const float4*)(s01 + q1);
                float4 g = *(const float4*)(s01 + q2);
                i0[0]=a.x; i0[1]=a.y; i0[2]=b.x; i0[3]=b.y; i0[4]=g.x; i0[5]=g.y;
                i1[0]=a.z; i1[1]=a.w; i1[2]=b.z; i1[3]=b.w; i1[4]=g.z; i1[5]=g.w;
                const float* s2 = sm + OFF_I2;
                float2 c0 = *(const float2*)(s2 + p0);
                float2 c1 = *(const float2*)(s2 + p1);
                float2 c2 = *(const float2*)(s2 + p2);
                i2[0]=c0.x; i2[1]=c0.y; i2[2]=c1.x; i2[3]=c1.y; i2[4]=c2.x; i2[5]=c2.y;
            }

            // weights + accumulation
            #pragma unroll
            for (int tt = 0; tt < TT; ++tt) {
                #pragma unroll
                for (int dt = 0; dt < 5; ++dt) {
                    const int l = tt + dt;
                    float e = dot2[tt][dt] - Pn[l];
                    e = f[tt][dt] ? -350.0f : e;     // fail -> weight == +0
                    float wgt;
                    asm("ex2.approx.f32 %0, %1;" : "=f"(wgt) : "f"(e));
                    den[tt]  += wgt;
                    num0[tt] = fmaf(wgt, i0[l], num0[tt]);
                    num1[tt] = fmaf(wgt, i1[l], num1[tt]);
                    num2[tt] = fmaf(wgt, i2[l], num2[tt]);
                }
            }
        }

        if (++dx == 7) { dx = 0; ++dy; }
    }

    // ---------------- cross-group reduction through smem -----------------
    __syncthreads();   // everyone done reading the tile
    if (og != 0) {
        int p = ((og - 1) * 192 + lt) * 9;       // stride 9: conflict-light
        sm[p + 0] = num0[0]; sm[p + 1] = num0[1];
        sm[p + 2] = num1[0]; sm[p + 3] = num1[1];
        sm[p + 4] = num2[0]; sm[p + 5] = num2[1];
        sm[p + 6] = den[0];  sm[p + 7] = den[1];
    }
    __syncthreads();

    // ---------------- write out (group 0 only) ----------------
    if (og == 0) {
        #pragma unroll
        for (int g = 0; g < 3; ++g) {
            int p = (g * 192 + lt) * 9;
            num0[0] += sm[p + 0]; num0[1] += sm[p + 1];
            num1[0] += sm[p + 2]; num1[1] += sm[p + 3];
            num2[0] += sm[p + 4]; num2[1] += sm[p + 5];
            den[0]  += sm[p + 6]; den[1]  += sm[p + 7];
        }

        const int hh = h0 + ty;
        const int ww = w0 + tx;
        #pragma unroll
        for (int tt = 0; tt < TT; ++tt) {
            int t = t0 + tgb + tt;
            float inv = 1.0f / den[tt];
            int base = (hh * W + ww) * T + t;
            out[base]            = num0[tt] * inv;
            out[HWT + base]      = num1[tt] * inv;
            out[2 * HWT + base]  = num2[tt] * inv;
        }
    }
}

extern "C" void kernel_launch(void* const* d_in, const int* in_sizes, int n_in,
                              void* d_out, int out_size)
{
    const float* images   = (const float*)d_in[0];
    const float* guidance = (const float*)d_in[1];
    const float* estim    = (const float*)d_in[2];
    const float* var      = (const float*)d_in[3];
    const float* sig      = (const float*)d_in[4];
    const int*   spp      = (const int*)d_in[5];
    float* out = (float*)d_out;

    cudaFuncSetAttribute(denoise_kernel,
                         cudaFuncAttributeMaxDynamicSharedMemorySize,
                         SMEM_FLOATS * (int)sizeof(float));

    dim3 grid(W / OW, H / OH, T / OT);   // 64 x 32 x 4
    denoise_kernel<<<grid, NTHREADS, SMEM_FLOATS * sizeof(float)>>>(
        images, guidance, estim, var, sig, spp, out);
}

// round 16
// speedup vs baseline: 1.6642x; 1.0944x over previous
#include <cuda_runtime.h>
#include <math.h>

#define H 256
#define W 256
#define T 48
#define HWT (H*W*T)

// Output tile per block
#define OH 8
#define OW 4
#define OT 12
#define TT 2            // t-outputs per thread (register blocking)
#define NTHREADS 768    // 4 og x (6 tg x 8 ty x 4 tx)

// Halo'ed SMEM tile
#define HY 14           // OH + 6
#define HX 10           // OW + 6
#define HT 16           // t-slots per voxel
#define ROWS (HY*HX)    // 140
#define QSTRIDE 32      // quad-plane voxel stride (floats): 8 quads
#define PSTRIDE 16      // pair-plane voxel stride (floats)
#define QPLANE (ROWS*QSTRIDE)  // 4480
#define PPLANE (ROWS*PSTRIDE)  // 2240

// float offsets of the channel groups
#define OFF_G01 0                     // guidance ch0/ch1 interleaved quads
#define OFF_EV0 (4*QPLANE)            // [e,e,v,v] quads, ch0..2
#define OFF_I01 (7*QPLANE)            // image ch0/ch1 interleaved quads
#define OFF_G8  (8*QPLANE)            // guidance ch8, pair layout
#define OFF_I2  (OFF_G8 + PPLANE)     // image ch2, pair layout
#define OFF_P   (OFF_I2 + PPLANE)     // neighbor norms, pair layout
#define SMEM_FLOATS (OFF_P + PPLANE)  // 42560 floats -> 170240 bytes

#define NPOS (ROWS*8)   // 1120 (voxel, t-pair) positions

#define NL (TT + 4)     // 6 t-lanes used per row

// pair-plane rotation (16-lane phase = 4ty x 4tx): conflict-free LDS.64
#define PHI2(x, y) (((((x) >> 1) & 1) + (((y) & 3) << 1)) << 1)
// quad-plane rotation (8-lane phase = 2ty x 4tx): bijection per phase
#define RHO8(x, y) (((((y) & 1) << 2) | ((x) & 3)))

__global__ __launch_bounds__(NTHREADS, 1)
void denoise_kernel(const float* __restrict__ images,
                    const float* __restrict__ guidance,
                    const float* __restrict__ estimands,
                    const float* __restrict__ variance,
                    const float* __restrict__ sigma_inv,
                    const int*   __restrict__ spp_ptr,
                    float* __restrict__ out)
{
    extern __shared__ float sm[];
    __shared__ float ssig[9];   // sqrt(sigma_inv[c] * log2(e))

    const int tid = threadIdx.x;
    const int w0 = blockIdx.x * OW;
    const int h0 = blockIdx.y * OH;
    const int t0 = blockIdx.z * OT;

    if (tid < 9) {
        ssig[tid] = sqrtf(__fmul_rn(sigma_inv[tid], 1.4426950408889634f));
    }
    const float sppf = (float)spp_ptr[0];
    const float T2f  = (float)(2.8070337683438042 * 2.8070337683438042);
    // spp is a power of two (64): dividing both sides by spp is EXACT, so
    //   rnd(rnd(d^2)*spp) > rnd(T2*s)  <=>  rnd(d^2) > rnd((T2/spp)*s)
    const float T2d  = T2f / sppf;
    __syncthreads();

    // ---------------- cooperative fill: per-position, channels hoisted ---
    for (int pos = tid; pos < NPOS; pos += NTHREADS) {
        int jp    = pos & 7;
        int rowid = pos >> 3;
        int y  = rowid / HX;
        int x  = rowid - y * HX;
        int hg = h0 + y - 3;
        int wg = w0 + x - 3;
        int tg_ = t0 + (jp << 1) - 2;    // even
        bool inb = ((unsigned)hg < H) & ((unsigned)wg < W) & ((unsigned)tg_ < T);
        int gidx = (hg * W + wg) * T + tg_;
        int qoff = rowid * QSTRIDE + (((jp + RHO8(x, y)) & 7) << 2);
        int poff = rowid * PSTRIDE + (((jp << 1) + PHI2(x, y)) & 15);

        float2 gs[9];
        float2 P2; P2.x = 0.f; P2.y = 0.f;
        #pragma unroll
        for (int c = 0; c < 9; ++c) {
            float2 v; v.x = 0.f; v.y = 0.f;
            if (inb) {
                float2 g = *(const float2*)(guidance + c * HWT + gidx);
                v.x = g.x * ssig[c]; v.y = g.y * ssig[c];
            }
            gs[c] = v;
            P2.x = fmaf(v.x, v.x, P2.x);
            P2.y = fmaf(v.y, v.y, P2.y);
        }
        #pragma unroll
        for (int cp = 0; cp < 4; ++cp) {
            float4 q;
            q.x = gs[2*cp].x;   q.y = gs[2*cp].y;
            q.z = gs[2*cp+1].x; q.w = gs[2*cp+1].y;
            *(float4*)(sm + OFF_G01 + cp * QPLANE + qoff) = q;
        }
        *(float2*)(sm + OFF_G8 + poff) = gs[8];
        *(float2*)(sm + OFF_P  + poff) = P2;

        #pragma unroll
        for (int c = 0; c < 3; ++c) {
            float2 e; e.x = -2.f; e.y = -2.f;    // estimand pad
            float2 v; v.x = 0.f;  v.y = 0.f;
            if (inb) {
                e = *(const float2*)(estimands + c * HWT + gidx);
                v = *(const float2*)(variance  + c * HWT + gidx);
            }
            float4 q; q.x = e.x; q.y = e.y; q.z = v.x; q.w = v.y;
            *(float4*)(sm + OFF_EV0 + c * QPLANE + qoff) = q;
        }

        {
            float2 a; a.x = 0.f; a.y = 0.f;
            float2 b; b.x = 0.f; b.y = 0.f;
            float2 cc; cc.x = 0.f; cc.y = 0.f;
            if (inb) {
                a  = *(const float2*)(images + 0 * HWT + gidx);
                b  = *(const float2*)(images + 1 * HWT + gidx);
                cc = *(const float2*)(images + 2 * HWT + gidx);
            }
            float4 q; q.x = a.x; q.y = a.y; q.z = b.x; q.w = b.y;
            *(float4*)(sm + OFF_I01 + qoff) = q;
            *(float2*)(sm + OFF_I2 + poff) = cc;
        }
    }
    __syncthreads();

    // ---------------- per-thread decomposition ----------------
    const int wg_id = tid >> 5;            // 0..23
    const int og  = wg_id / 6;             // 0..3
    const int tg  = wg_id - og * 6;        // 0..5
    const int rr  = tid & 31;
    const int ty  = rr >> 2;               // 0..7
    const int tx  = rr & 3;                // 0..3
    const int tgb = tg * TT;               // even
    const int kb  = tg;                    // t-pair base = tgb/2
    const int lt  = tg * 32 + rr;          // 0..191 within og
    const int o0  = (og * 49) >> 2;        // 0,12,24,36
    const int o1  = ((og + 1) * 49) >> 2;  // 12,24,36,49

    // center values: gc DOUBLED (exact x2) for the seeded-dot trick
    float gc2[9][TT], ec[3][TT], vc[3][TT], negPc[TT];
    {
        int xc = tx + 3, yc = ty + 3;
        int rowc = yc * HX + xc;
        int qc = rowc * QSTRIDE + (((kb + 1 + RHO8(xc, yc)) & 7) << 2);
        int pc = rowc * PSTRIDE + ((tgb + 2 + PHI2(xc, yc)) & 15);
        #pragma unroll
        for (int cp = 0; cp < 4; ++cp) {
            float4 q = *(const float4*)(sm + OFF_G01 + cp * QPLANE + qc);
            gc2[2*cp][0]   = 2.0f * q.x; gc2[2*cp][1]   = 2.0f * q.y;
            gc2[2*cp+1][0] = 2.0f * q.z; gc2[2*cp+1][1] = 2.0f * q.w;
        }
        {
            float2 g = *(const float2*)(sm + OFF_G8 + pc);
            gc2[8][0] = 2.0f * g.x; gc2[8][1] = 2.0f * g.y;
        }
        #pragma unroll
        for (int c = 0; c < 3; ++c) {
            float4 q = *(const float4*)(sm + OFF_EV0 + c * QPLANE + qc);
            ec[c][0] = q.x; ec[c][1] = q.y;
            vc[c][0] = q.z; vc[c][1] = q.w;
        }
        float2 p = *(const float2*)(sm + OFF_P + pc);
        negPc[0] = -p.x; negPc[1] = -p.y;
    }

    float num0[TT], num1[TT], num2[TT], den[TT];
    #pragma unroll
    for (int tt = 0; tt < TT; ++tt) { num0[tt] = 0.f; num1[tt] = 0.f; num2[tt] = 0.f; den[tt] = 0.f; }

    // ---------------- main loop over this group's spatial offsets --------
    int dy = o0 / 7, dx = o0 - 7 * (o0 / 7);
    #pragma unroll 1
    for (int o = o0; o < o1; ++o) {
        int y = ty + dy;
        int x = tx + dx;
        int rowid = y * HX + x;
        int rq = rowid * QSTRIDE;
        int rp = rowid * PSTRIDE;
        int r8 = RHO8(x, y);
        int q0 = rq + (((kb + 0 + r8) & 7) << 2);
        int q1 = rq + (((kb + 1 + r8) & 7) << 2);
        int q2 = rq + (((kb + 2 + r8) & 7) << 2);
        int ph = PHI2(x, y);
        int p0 = rp + ((tgb + 0 + ph) & 15);
        int p1 = rp + ((tgb + 2 + ph) & 15);
        int p2 = rp + ((tgb + 4 + ph) & 15);

        // ---- z-test FIRST (bit-exact), one LDS.128 per (channel, quad) ----
        int f[TT][5];
        #pragma unroll
        for (int tt = 0; tt < TT; ++tt)
            #pragma unroll
            for (int dt = 0; dt < 5; ++dt) f[tt][dt] = 0;

        #pragma unroll
        for (int c = 0; c < 3; ++c) {
            const float* se = sm + OFF_EV0 + c * QPLANE;
            float4 a = *(const float4*)(se + q0);
            float4 b = *(const float4*)(se + q1);
            float4 g = *(const float4*)(se + q2);
            float er[NL] = { a.x, a.y, b.x, b.y, g.x, g.y };
            float vr[NL] = { a.z, a.w, b.z, b.w, g.z, g.w };
            #pragma unroll
            for (int tt = 0; tt < TT; ++tt) {
                #pragma unroll
                for (int dt = 0; dt < 5; ++dt) {
                    const int l = tt + dt;
                    float d = __fsub_rn(er[l], ec[c][tt]);
                    float q = __fmul_rn(d, d);
                    float rv = __fmul_rn(T2d, __fadd_rn(vr[l], vc[c][tt]));
                    f[tt][dt] |= (q > rv);
                }
            }
        }

        int allfail = f[0][0] & f[0][1] & f[0][2] & f[0][3] & f[0][4]
                    & f[1][0] & f[1][1] & f[1][2] & f[1][3] & f[1][4];

        // Warp-uniform outer skip: skipped taps contribute exactly +0.
        if (__any_sync(0xffffffffu, !allfail)) {
            const int qa3[3] = { q0, q1, q2 };
            const int pa3[3] = { p0, p1, p2 };
            // Per-pair warp-vote guard: a tap passes somewhere in the warp
            // with prob ~0.08, so most pair-blocks are skipped entirely.
            #pragma unroll
            for (int tt = 0; tt < TT; ++tt) {
                #pragma unroll
                for (int dt = 0; dt < 5; ++dt) {
                    if (__any_sync(0xffffffffu, !f[tt][dt])) {
                        const int l  = tt + dt;
                        const int qa = qa3[l >> 1] + (l & 1);
                        const int pa = pa3[l >> 1] + (l & 1);
                        // seeded dot: exp2 arg = 2*dot - Pc - Pn
                        float dot2 = negPc[tt];
                        dot2 = fmaf(sm[OFF_G01 + 0*QPLANE + qa],     gc2[0][tt], dot2);
                        dot2 = fmaf(sm[OFF_G01 + 0*QPLANE + qa + 2], gc2[1][tt], dot2);
                        dot2 = fmaf(sm[OFF_G01 + 1*QPLANE + qa],     gc2[2][tt], dot2);
                        dot2 = fmaf(sm[OFF_G01 + 1*QPLANE + qa + 2], gc2[3][tt], dot2);
                        dot2 = fmaf(sm[OFF_G01 + 2*QPLANE + qa],     gc2[4][tt], dot2);
                        dot2 = fmaf(sm[OFF_G01 + 2*QPLANE + qa + 2], gc2[5][tt], dot2);
                        dot2 = fmaf(sm[OFF_G01 + 3*QPLANE + qa],     gc2[6][tt], dot2);
                        dot2 = fmaf(sm[OFF_G01 + 3*QPLANE + qa + 2], gc2[7][tt], dot2);
                        dot2 = fmaf(sm[OFF_G8 + pa],                 gc2[8][tt], dot2);
                        float e = dot2 - sm[OFF_P + pa];
                        e = f[tt][dt] ? -350.0f : e;   // fail -> weight == +0
                        float wgt;
                        asm("ex2.approx.f32 %0, %1;" : "=f"(wgt) : "f"(e));
                        den[tt]  += wgt;
                        num0[tt] = fmaf(wgt, sm[OFF_I01 + qa],     num0[tt]);
                        num1[tt] = fmaf(wgt, sm[OFF_I01 + qa + 2], num1[tt]);
                        num2[tt] = fmaf(wgt, sm[OFF_I2 + pa],      num2[tt]);
                    }
                }
            }
        }

        if (++dx == 7) { dx = 0; ++dy; }
    }

    // ---------------- cross-group reduction through smem -----------------
    __syncthreads();   // everyone done reading the tile
    if (og != 0) {
        int p = ((og - 1) * 192 + lt) * 9;       // stride 9: conflict-light
        sm[p + 0] = num0[0]; sm[p + 1] = num0[1];
        sm[p + 2] = num1[0]; sm[p + 3] = num1[1];
        sm[p + 4] = num2[0]; sm[p + 5] = num2[1];
        sm[p + 6] = den[0];  sm[p + 7] = den[1];
    }
    __syncthreads();

    // ---------------- write out (group 0 only) ----------------
    if (og == 0) {
        #pragma unroll
        for (int g = 0; g < 3; ++g) {
            int p = (g * 192 + lt) * 9;
            num0[0] += sm[p + 0]; num0[1] += sm[p + 1];
            num1[0] += sm[p + 2]; num1[1] += sm[p + 3];
            num2[0] += sm[p + 4]; num2[1] += sm[p + 5];
            den[0]  += sm[p + 6]; den[1]  += sm[p + 7];
        }

        const int hh = h0 + ty;
        const int ww = w0 + tx;
        #pragma unroll
        for (int tt = 0; tt < TT; ++tt) {
            int t = t0 + tgb + tt;
            float inv = 1.0f / den[tt];
            int base = (hh * W + ww) * T + t;
            out[base]            = num0[tt] * inv;
            out[HWT + base]      = num1[tt] * inv;
            out[2 * HWT + base]  = num2[tt] * inv;
        }
    }
}

extern "C" void kernel_launch(void* const* d_in, const int* in_sizes, int n_in,
                              void* d_out, int out_size)
{
    const float* images   = (const float*)d_in[0];
    const float* guidance = (const float*)d_in[1];
    const float* estim    = (const float*)d_in[2];
    const float* var      = (const float*)d_in[3];
    const float* sig      = (const float*)d_in[4];
    const int*   spp      = (const int*)d_in[5];
    float* out = (float*)d_out;

    cudaFuncSetAttribute(denoise_kernel,
                         cudaFuncAttributeMaxDynamicSharedMemorySize,
                         SMEM_FLOATS * (int)sizeof(float));

    dim3 grid(W / OW, H / OH, T / OT);   // 64 x 32 x 4
    denoise_kernel<<<grid, NTHREADS, SMEM_FLOATS * sizeof(float)>>>(
        images, guidance, estim, var, sig, spp, out);
}

// round 17
// speedup vs baseline: 1.7844x; 1.0723x over previous
#include <cuda_runtime.h>
#include <math.h>

#define H 256
#define W 256
#define T 48
#define HWT (H*W*T)

// Output tile per block
#define OH 8
#define OW 4
#define OT 12
#define TT 2            // t-outputs per thread (register blocking)
#define NTHREADS 768    // 4 og x (6 tg x 8 ty x 4 tx)

// Halo'ed SMEM tile (pure pair-plane layout)
#define HY 14           // OH + 6
#define HX 10           // OW + 6
#define HT 16           // t-slots per voxel
#define ROWS (HY*HX)    // 140
#define PLANE (ROWS*HT) // 2240
#define NCH 19          // 9 scaled-guidance + 3 est + 3 var + 3 img + 1 P
#define SMEM_FLOATS (NCH*PLANE)   // 42560 floats -> 170240 bytes
#define NPOS (ROWS*8)   // 1120 (voxel, t-pair) positions

#define NL (TT + 4)     // 6 t-lanes used per row

// pair-plane rotation (16-lane phase = 4ty x 4tx): conflict-free LDS.64,
// 2-way worst case for scalar LDS.32 (provable floor with even slots)
#define PHI2(x, y) (((((x) >> 1) & 1) + (((y) & 3) << 1)) << 1)

__global__ __launch_bounds__(NTHREADS, 1)
void denoise_kernel(const float* __restrict__ images,
                    const float* __restrict__ guidance,
                    const float* __restrict__ estimands,
                    const float* __restrict__ variance,
                    const float* __restrict__ sigma_inv,
                    const int*   __restrict__ spp_ptr,
                    float* __restrict__ out)
{
    extern __shared__ float sm[];
    __shared__ float ssig[9];   // sqrt(sigma_inv[c] * log2(e))

    const int tid = threadIdx.x;
    const int w0 = blockIdx.x * OW;
    const int h0 = blockIdx.y * OH;
    const int t0 = blockIdx.z * OT;

    if (tid < 9) {
        ssig[tid] = sqrtf(__fmul_rn(sigma_inv[tid], 1.4426950408889634f));
    }
    const float sppf = (float)spp_ptr[0];
    const float T2f  = (float)(2.8070337683438042 * 2.8070337683438042);
    // spp is a power of two (64): dividing both sides by spp is EXACT, so
    //   rnd(rnd(d^2)*spp) > rnd(T2*s)  <=>  rnd(d^2) > rnd((T2/spp)*s)
    const float T2d  = T2f / sppf;
    __syncthreads();

    // ---------------- cooperative fill: per-position, channels hoisted ---
    // guidance scaled by ssig; est/var RAW (bit-exact z-test); P (plane 18)
    // accumulated with the SAME ascending-c fmaf chain as the main-loop dot.
    for (int pos = tid; pos < NPOS; pos += NTHREADS) {
        int jp    = pos & 7;
        int rowid = pos >> 3;
        int y  = rowid / HX;
        int x  = rowid - y * HX;
        int hg = h0 + y - 3;
        int wg = w0 + x - 3;
        int tg_ = t0 + (jp << 1) - 2;    // even
        bool inb = ((unsigned)hg < H) & ((unsigned)wg < W) & ((unsigned)tg_ < T);
        int gidx = (hg * W + wg) * T + tg_;
        int slot = ((jp << 1) + PHI2(x, y)) & 15;   // even -> 8B aligned
        float* dst = sm + rowid * HT + slot;

        float2 P2; P2.x = 0.f; P2.y = 0.f;
        #pragma unroll
        for (int c = 0; c < 9; ++c) {
            float2 v; v.x = 0.f; v.y = 0.f;
            if (inb) {
                float2 g = *(const float2*)(guidance + c * HWT + gidx);
                v.x = g.x * ssig[c]; v.y = g.y * ssig[c];
            }
            *(float2*)(dst + c * PLANE) = v;
            P2.x = fmaf(v.x, v.x, P2.x);
            P2.y = fmaf(v.y, v.y, P2.y);
        }
        #pragma unroll
        for (int c = 0; c < 3; ++c) {
            float2 v; v.x = -2.f; v.y = -2.f;     // estimand pad
            if (inb) v = *(const float2*)(estimands + c * HWT + gidx);
            *(float2*)(dst + (9 + c) * PLANE) = v;
        }
        #pragma unroll
        for (int c = 0; c < 3; ++c) {
            float2 v; v.x = 0.f; v.y = 0.f;
            if (inb) v = *(const float2*)(variance + c * HWT + gidx);
            *(float2*)(dst + (12 + c) * PLANE) = v;
        }
        #pragma unroll
        for (int c = 0; c < 3; ++c) {
            float2 v; v.x = 0.f; v.y = 0.f;
            if (inb) v = *(const float2*)(images + c * HWT + gidx);
            *(float2*)(dst + (15 + c) * PLANE) = v;
        }
        *(float2*)(dst + 18 * PLANE) = P2;
    }
    __syncthreads();

    // ---------------- per-thread decomposition ----------------
    const int wg_id = tid >> 5;            // 0..23
    const int og  = wg_id / 6;             // 0..3
    const int tg  = wg_id - og * 6;        // 0..5
    const int rr  = tid & 31;
    const int ty  = rr >> 2;               // 0..7
    const int tx  = rr & 3;                // 0..3
    const int tgb = tg * TT;               // even
    const int lt  = tg * 32 + rr;          // 0..191 within og
    const int o0  = (og * 49) >> 2;        // 0,12,24,36
    const int o1  = ((og + 1) * 49) >> 2;  // 12,24,36,49

    // center values: gc DOUBLED (exact x2) for the seeded-dot trick
    float gc2[9][TT], ec[3][TT], vc[3][TT], negPc[TT];
    {
        int xc = tx + 3, yc = ty + 3;
        int slc = (yc * HX + xc) * HT + ((tgb + 2 + PHI2(xc, yc)) & 15);
        #pragma unroll
        for (int c = 0; c < 9; ++c) {
            float2 g = *(const float2*)(sm + c * PLANE + slc);
            gc2[c][0] = 2.0f * g.x; gc2[c][1] = 2.0f * g.y;
        }
        #pragma unroll
        for (int c = 0; c < 3; ++c) {
            float2 e = *(const float2*)(sm + (9 + c) * PLANE + slc);
            ec[c][0] = e.x; ec[c][1] = e.y;
        }
        #pragma unroll
        for (int c = 0; c < 3; ++c) {
            float2 v = *(const float2*)(sm + (12 + c) * PLANE + slc);
            vc[c][0] = v.x; vc[c][1] = v.y;
        }
        float2 p = *(const float2*)(sm + 18 * PLANE + slc);
        negPc[0] = -p.x; negPc[1] = -p.y;
    }

    float num0[TT], num1[TT], num2[TT], den[TT];
    #pragma unroll
    for (int tt = 0; tt < TT; ++tt) { num0[tt] = 0.f; num1[tt] = 0.f; num2[tt] = 0.f; den[tt] = 0.f; }

    // ---------------- main loop over this group's spatial offsets --------
    int dy = o0 / 7, dx = o0 - 7 * (o0 / 7);
    #pragma unroll 1
    for (int o = o0; o < o1; ++o) {
        int y = ty + dy;
        int x = tx + dx;
        int rowoff = (y * HX + x) * HT;
        int ph = PHI2(x, y);
        // three even pair bases, contiguous 8B each (wrap never splits a pair)
        int p0 = rowoff + ((tgb + 0 + ph) & 15);
        int p1 = rowoff + ((tgb + 2 + ph) & 15);
        int p2 = rowoff + ((tgb + 4 + ph) & 15);

        // ---- z-test FIRST (bit-exact), pair LDS.64 loads ----
        int f[TT][5];
        #pragma unroll
        for (int tt = 0; tt < TT; ++tt)
            #pragma unroll
            for (int dt = 0; dt < 5; ++dt) f[tt][dt] = 0;

        #pragma unroll
        for (int c = 0; c < 3; ++c) {
            const float* se = sm + (9 + c)  * PLANE;
            const float* sv = sm + (12 + c) * PLANE;
            float2 e0 = *(const float2*)(se + p0);
            float2 e1 = *(const float2*)(se + p1);
            float2 e2 = *(const float2*)(se + p2);
            float2 v0 = *(const float2*)(sv + p0);
            float2 v1 = *(const float2*)(sv + p1);
            float2 v2 = *(const float2*)(sv + p2);
            float er[NL] = { e0.x, e0.y, e1.x, e1.y, e2.x, e2.y };
            float vr[NL] = { v0.x, v0.y, v1.x, v1.y, v2.x, v2.y };
            #pragma unroll
            for (int tt = 0; tt < TT; ++tt) {
                #pragma unroll
                for (int dt = 0; dt < 5; ++dt) {
                    const int l = tt + dt;
                    float d = __fsub_rn(er[l], ec[c][tt]);
                    float q = __fmul_rn(d, d);
                    float rv = __fmul_rn(T2d, __fadd_rn(vr[l], vc[c][tt]));
                    f[tt][dt] |= (q > rv);
                }
            }
        }

        int allfail = f[0][0] & f[0][1] & f[0][2] & f[0][3] & f[0][4]
                    & f[1][0] & f[1][1] & f[1][2] & f[1][3] & f[1][4];

        // Warp-uniform outer skip: skipped taps contribute exactly +0.
        if (__any_sync(0xffffffffu, !allfail)) {
            const int pa3[3] = { p0, p1, p2 };
            // Per-pair warp-vote guard: a tap passes somewhere in the warp
            // with prob ~0.08, so most pair-blocks are skipped entirely.
            #pragma unroll
            for (int tt = 0; tt < TT; ++tt) {
                #pragma unroll
                for (int dt = 0; dt < 5; ++dt) {
                    if (__any_sync(0xffffffffu, !f[tt][dt])) {
                        const int l  = tt + dt;
                        const int pa = pa3[l >> 1] + (l & 1);
                        // seeded dot: exp2 arg = 2*dot - Pc - Pn
                        float dot2 = negPc[tt];
                        dot2 = fmaf(sm[0 * PLANE + pa], gc2[0][tt], dot2);
                        dot2 = fmaf(sm[1 * PLANE + pa], gc2[1][tt], dot2);
                        dot2 = fmaf(sm[2 * PLANE + pa], gc2[2][tt], dot2);
                        dot2 = fmaf(sm[3 * PLANE + pa], gc2[3][tt], dot2);
                        dot2 = fmaf(sm[4 * PLANE + pa], gc2[4][tt], dot2);
                        dot2 = fmaf(sm[5 * PLANE + pa], gc2[5][tt], dot2);
                        dot2 = fmaf(sm[6 * PLANE + pa], gc2[6][tt], dot2);
                        dot2 = fmaf(sm[7 * PLANE + pa], gc2[7][tt], dot2);
                        dot2 = fmaf(sm[8 * PLANE + pa], gc2[8][tt], dot2);
                        float e = dot2 - sm[18 * PLANE + pa];
                        e = f[tt][dt] ? -350.0f : e;   // fail -> weight == +0
                        float wgt;
                        asm("ex2.approx.f32 %0, %1;" : "=f"(wgt) : "f"(e));
                        den[tt]  += wgt;
                        num0[tt] = fmaf(wgt, sm[15 * PLANE + pa], num0[tt]);
                        num1[tt] = fmaf(wgt, sm[16 * PLANE + pa], num1[tt]);
                        num2[tt] = fmaf(wgt, sm[17 * PLANE + pa], num2[tt]);
                    }
                }
            }
        }

        if (++dx == 7) { dx = 0; ++dy; }
    }

    // ---------------- cross-group reduction through smem -----------------
    __syncthreads();   // everyone done reading the tile
    if (og != 0) {
        int p = ((og - 1) * 192 + lt) * 9;       // stride 9: conflict-light
        sm[p + 0] = num0[0]; sm[p + 1] = num0[1];
        sm[p + 2] = num1[0]; sm[p + 3] = num1[1];
        sm[p + 4] = num2[0]; sm[p + 5] = num2[1];
        sm[p + 6] = den[0];  sm[p + 7] = den[1];
    }
    __syncthreads();

    // ---------------- write out (group 0 only) ----------------
    if (og == 0) {
        #pragma unroll
        for (int g = 0; g < 3; ++g) {
            int p = (g * 192 + lt) * 9;
            num0[0] += sm[p + 0]; num0[1] += sm[p + 1];
            num1[0] += sm[p + 2]; num1[1] += sm[p + 3];
            num2[0] += sm[p + 4]; num2[1] += sm[p + 5];
            den[0]  += sm[p + 6]; den[1]  += sm[p + 7];
        }

        const int hh = h0 + ty;
        const int ww = w0 + tx;
        #pragma unroll
        for (int tt = 0; tt < TT; ++tt) {
            int t = t0 + tgb + tt;
            float inv = 1.0f / den[tt];
            int base = (hh * W + ww) * T + t;
            out[base]            = num0[tt] * inv;
            out[HWT + base]      = num1[tt] * inv;
            out[2 * HWT + base]  = num2[tt] * inv;
        }
    }
}

extern "C" void kernel_launch(void* const* d_in, const int* in_sizes, int n_in,
                              void* d_out, int out_size)
{
    const float* images   = (const float*)d_in[0];
    const float* guidance = (const float*)d_in[1];
    const float* estim    = (const float*)d_in[2];
    const float* var      = (const float*)d_in[3];
    const float* sig      = (const float*)d_in[4];
    const int*   spp      = (const int*)d_in[5];
    float* out = (float*)d_out;

    cudaFuncSetAttribute(denoise_kernel,
                         cudaFuncAttributeMaxDynamicSharedMemorySize,
                         SMEM_FLOATS * (int)sizeof(float));

    dim3 grid(W / OW, H / OH, T / OT);   // 64 x 32 x 4
    denoise_kernel<<<grid, NTHREADS, SMEM_FLOATS * sizeof(float)>>>(
        images, guidance, estim, var, sig, spp, out);
}